// round 2
// baseline (speedup 1.0000x reference)
#include <cuda_runtime.h>
#include <math.h>

#define NN 100000
#define EE 1600000
#define HH 128
#define PP 10
#define TT 138              // PP + HH
#define SCALE 0.08838834764831845f   // 1/sqrt(128)

// ---------------- scratch (static __device__, no allocs) ----------------
__device__ float g_X[NN * TT];      // concat(physics, emb)
__device__ float g_Q[NN * HH];
__device__ float g_K[NN * HH];
__device__ float g_V[NN * HH];
__device__ float g_exps[EE];
__device__ float g_agg[NN * HH];
__device__ int   g_cnt[NN];
__device__ int   g_off[NN];
__device__ int   g_perm[EE];
__device__ int   g_bsum[32];

// ---------------- init ----------------
__global__ void zero_cnt_kernel() {
    int i = blockIdx.x * blockDim.x + threadIdx.x;
    if (i < NN) g_cnt[i] = 0;
}

__global__ void build_x_kernel(const float* __restrict__ phys,
                               const float* __restrict__ emb) {
    int idx = blockIdx.x * blockDim.x + threadIdx.x;
    if (idx >= NN * TT) return;
    int n = idx / TT;
    int c = idx - n * TT;
    g_X[idx] = (c < PP) ? phys[n * PP + c] : emb[n * HH + (c - PP)];
}

// ---------------- fp32 GEMM: C[N,128] = A[N,Kdim] @ W[Kdim,128] + bias ----
// BM=64, BN=128, BK=8, 256 threads; thread microtile 8 rows x 4 cols.
__global__ void __launch_bounds__(256) gemm_kernel(
    const float* __restrict__ A, int Kdim,
    const float* __restrict__ W, const float* __restrict__ bias,
    float* __restrict__ C)
{
    __shared__ __align__(16) float As[8][64];
    __shared__ __align__(16) float Ws[8][128];

    int tid = threadIdx.x;
    int tx = tid & 31;          // col group (4 cols)
    int ty = tid >> 5;          // row group (8 rows)
    int blockM = blockIdx.x * 64;

    float c[8][4];
#pragma unroll
    for (int i = 0; i < 8; i++)
#pragma unroll
        for (int j = 0; j < 4; j++) c[i][j] = 0.f;

    int am = (tid * 2) >> 3;    // 0..63
    int ak = (tid * 2) & 7;     // 0,2,4,6
    int gm = blockM + am;
    int wk = tid >> 5;          // 0..7
    int wn = (tid & 31) * 4;

    for (int kk = 0; kk < Kdim; kk += 8) {
        float a0 = 0.f, a1 = 0.f;
        if (gm < NN) {
            if (kk + ak < Kdim)     a0 = A[gm * Kdim + kk + ak];
            if (kk + ak + 1 < Kdim) a1 = A[gm * Kdim + kk + ak + 1];
        }
        As[ak][am]     = a0;
        As[ak + 1][am] = a1;

        float4 w = make_float4(0.f, 0.f, 0.f, 0.f);
        if (kk + wk < Kdim) w = *(const float4*)&W[(kk + wk) * HH + wn];
        *(float4*)&Ws[wk][wn] = w;
        __syncthreads();

#pragma unroll
        for (int k = 0; k < 8; k++) {
            float4 b  = *(const float4*)&Ws[k][tx * 4];
            float4 p0 = *(const float4*)&As[k][ty * 8];
            float4 p1 = *(const float4*)&As[k][ty * 8 + 4];
            float a[8] = {p0.x, p0.y, p0.z, p0.w, p1.x, p1.y, p1.z, p1.w};
#pragma unroll
            for (int i = 0; i < 8; i++) {
                c[i][0] += a[i] * b.x;
                c[i][1] += a[i] * b.y;
                c[i][2] += a[i] * b.z;
                c[i][3] += a[i] * b.w;
            }
        }
        __syncthreads();
    }

    float4 bb = *(const float4*)&bias[tx * 4];
#pragma unroll
    for (int i = 0; i < 8; i++) {
        int m = blockM + ty * 8 + i;
        if (m < NN) {
            float4 o = make_float4(c[i][0] + bb.x, c[i][1] + bb.y,
                                   c[i][2] + bb.z, c[i][3] + bb.w);
            *(float4*)&C[m * HH + tx * 4] = o;
        }
    }
}

// ---------------- edge scores: exp(Q[dst].K[src]*scale), histogram dst ----
__global__ void __launch_bounds__(256) edge_score_kernel(
    const int* __restrict__ src, const int* __restrict__ dst)
{
    int w = blockIdx.x * 8 + (threadIdx.x >> 5);
    if (w >= EE) return;
    int lane = threadIdx.x & 31;
    int s = src[w];
    int d = dst[w];
    float4 q = *(const float4*)&g_Q[d * HH + lane * 4];
    float4 k = *(const float4*)&g_K[s * HH + lane * 4];
    float p = q.x * k.x + q.y * k.y + q.z * k.z + q.w * k.w;
#pragma unroll
    for (int o = 16; o > 0; o >>= 1) p += __shfl_xor_sync(0xffffffffu, p, o);
    if (lane == 0) {
        g_exps[w] = expf(p * SCALE);
        atomicAdd(&g_cnt[d], 1);
    }
}

// ---------------- exclusive scan of g_cnt -> g_off (3 kernels) ----------
// chunk 4096/block, 25 blocks for N=100000
__global__ void __launch_bounds__(256) scanA_kernel() {
    __shared__ int wsumI[8];
    int base = blockIdx.x * 4096;
    int t = threadIdx.x;
    int idx0 = base + t * 16;
    int vals[16];
    int s = 0;
#pragma unroll
    for (int j = 0; j < 16; j++) {
        int idx = idx0 + j;
        int v = (idx < NN) ? g_cnt[idx] : 0;
        vals[j] = s;
        s += v;
    }
    int lane = t & 31, wid = t >> 5;
    int incl = s;
#pragma unroll
    for (int o = 1; o < 32; o <<= 1) {
        int v = __shfl_up_sync(0xffffffffu, incl, o);
        if (lane >= o) incl += v;
    }
    if (lane == 31) wsumI[wid] = incl;
    __syncthreads();
    if (wid == 0) {
        int w = (lane < 8) ? wsumI[lane] : 0;
#pragma unroll
        for (int o = 1; o < 8; o <<= 1) {
            int v = __shfl_up_sync(0xffffffffu, w, o);
            if (lane >= o) w += v;
        }
        if (lane < 8) wsumI[lane] = w;
    }
    __syncthreads();
    int texcl = (incl - s) + (wid > 0 ? wsumI[wid - 1] : 0);
#pragma unroll
    for (int j = 0; j < 16; j++) {
        int idx = idx0 + j;
        if (idx < NN) g_off[idx] = texcl + vals[j];
    }
    if (t == 0) g_bsum[blockIdx.x] = wsumI[7];
}

__global__ void scanB_kernel() {
    if (threadIdx.x == 0) {
        int s = 0;
#pragma unroll
        for (int i = 0; i < 25; i++) { int v = g_bsum[i]; g_bsum[i] = s; s += v; }
    }
}

__global__ void __launch_bounds__(256) scanC_kernel() {
    int add = g_bsum[blockIdx.x];
    int idx0 = blockIdx.x * 4096 + threadIdx.x * 16;
#pragma unroll
    for (int j = 0; j < 16; j++) {
        int idx = idx0 + j;
        if (idx < NN) g_off[idx] += add;
    }
}

// ---------------- scatter edge ids into CSR (mutates g_off) -------------
// afterwards: segment(n) = [ (n==0?0:g_off[n-1]) , g_off[n] )
__global__ void __launch_bounds__(256) scatter_kernel(const int* __restrict__ dst) {
    int e = blockIdx.x * blockDim.x + threadIdx.x;
    if (e >= EE) return;
    int d = dst[e];
    int p = atomicAdd(&g_off[d], 1);
    g_perm[p] = e;
}

// ---------------- per-node softmax + message aggregation ----------------
__global__ void __launch_bounds__(256) aggregate_kernel(const int* __restrict__ src) {
    int n = blockIdx.x * 8 + (threadIdx.x >> 5);
    if (n >= NN) return;
    int lane = threadIdx.x & 31;
    int end = g_off[n];
    int start = (n == 0) ? 0 : g_off[n - 1];

    float den = 0.f;
    for (int i = start + lane; i < end; i += 32) den += g_exps[g_perm[i]];
#pragma unroll
    for (int o = 16; o > 0; o >>= 1) den += __shfl_xor_sync(0xffffffffu, den, o);
    float invden = 1.f / (den + 1e-8f);

    float4 acc = make_float4(0.f, 0.f, 0.f, 0.f);
    for (int base = start; base < end; base += 32) {
        int i = base + lane;
        float w = 0.f; int sidx = 0;
        if (i < end) {
            int e = g_perm[i];
            w = g_exps[e] * invden;
            sidx = src[e];
        }
        int cnt = min(32, end - base);
        for (int j = 0; j < cnt; j++) {
            float wj = __shfl_sync(0xffffffffu, w, j);
            int   sj = __shfl_sync(0xffffffffu, sidx, j);
            float4 v = *(const float4*)&g_V[sj * HH + lane * 4];
            acc.x += wj * v.x; acc.y += wj * v.y;
            acc.z += wj * v.z; acc.w += wj * v.w;
        }
    }
    *(float4*)&g_agg[n * HH + lane * 4] = acc;
}

// ---------------- O-GEMM + residual + LayerNorm fused -------------------
__global__ void __launch_bounds__(256) gemm_ln_kernel(
    const float* __restrict__ W, const float* __restrict__ bias,
    const float* __restrict__ emb, const float* __restrict__ gamma,
    const float* __restrict__ beta, float* __restrict__ out)
{
    __shared__ __align__(16) float As[8][64];
    __shared__ __align__(16) float Ws[8][128];

    int tid = threadIdx.x;
    int tx = tid & 31;
    int ty = tid >> 5;
    int blockM = blockIdx.x * 64;

    float c[8][4];
#pragma unroll
    for (int i = 0; i < 8; i++)
#pragma unroll
        for (int j = 0; j < 4; j++) c[i][j] = 0.f;

    int am = (tid * 2) >> 3;
    int ak = (tid * 2) & 7;
    int gm = blockM + am;
    int wk = tid >> 5;
    int wn = (tid & 31) * 4;

    for (int kk = 0; kk < HH; kk += 8) {
        float a0 = 0.f, a1 = 0.f;
        if (gm < NN) {
            a0 = g_agg[gm * HH + kk + ak];
            a1 = g_agg[gm * HH + kk + ak + 1];
        }
        As[ak][am]     = a0;
        As[ak + 1][am] = a1;
        float4 w = *(const float4*)&W[(kk + wk) * HH + wn];
        *(float4*)&Ws[wk][wn] = w;
        __syncthreads();
#pragma unroll
        for (int k = 0; k < 8; k++) {
            float4 b  = *(const float4*)&Ws[k][tx * 4];
            float4 p0 = *(const float4*)&As[k][ty * 8];
            float4 p1 = *(const float4*)&As[k][ty * 8 + 4];
            float a[8] = {p0.x, p0.y, p0.z, p0.w, p1.x, p1.y, p1.z, p1.w};
#pragma unroll
            for (int i = 0; i < 8; i++) {
                c[i][0] += a[i] * b.x;
                c[i][1] += a[i] * b.y;
                c[i][2] += a[i] * b.z;
                c[i][3] += a[i] * b.w;
            }
        }
        __syncthreads();
    }

    float4 bb = *(const float4*)&bias[tx * 4];
    float4 gm4 = *(const float4*)&gamma[tx * 4];
    float4 bt4 = *(const float4*)&beta[tx * 4];

#pragma unroll
    for (int i = 0; i < 8; i++) {
        int m = blockM + ty * 8 + i;
        if (m < NN) {
            float4 e = *(const float4*)&emb[m * HH + tx * 4];
            float x0 = c[i][0] + bb.x + e.x;
            float x1 = c[i][1] + bb.y + e.y;
            float x2 = c[i][2] + bb.z + e.z;
            float x3 = c[i][3] + bb.w + e.w;
            float s = x0 + x1 + x2 + x3;
            float q = x0 * x0 + x1 * x1 + x2 * x2 + x3 * x3;
#pragma unroll
            for (int o = 16; o > 0; o >>= 1) {
                s += __shfl_xor_sync(0xffffffffu, s, o);
                q += __shfl_xor_sync(0xffffffffu, q, o);
            }
            float mean = s * (1.f / 128.f);
            float var  = q * (1.f / 128.f) - mean * mean;
            float r = rsqrtf(var + 1e-5f);
            float4 o4 = make_float4(gm4.x * (x0 - mean) * r + bt4.x,
                                    gm4.y * (x1 - mean) * r + bt4.y,
                                    gm4.z * (x2 - mean) * r + bt4.z,
                                    gm4.w * (x3 - mean) * r + bt4.w);
            *(float4*)&out[m * HH + tx * 4] = o4;
        }
    }
}

// ---------------- launch ----------------
extern "C" void kernel_launch(void* const* d_in, const int* in_sizes, int n_in,
                              void* d_out, int out_size)
{
    const float* phys  = (const float*)d_in[0];
    const float* emb   = (const float*)d_in[1];
    const int*   eidx  = (const int*)  d_in[2];
    const float* Wq    = (const float*)d_in[3];
    const float* bq    = (const float*)d_in[4];
    const float* Wk    = (const float*)d_in[5];
    const float* bk    = (const float*)d_in[6];
    const float* Wv    = (const float*)d_in[7];
    const float* bv    = (const float*)d_in[8];
    const float* Wo    = (const float*)d_in[9];
    const float* bo    = (const float*)d_in[10];
    const float* gamma = (const float*)d_in[11];
    const float* beta  = (const float*)d_in[12];
    float* out = (float*)d_out;

    const int* src = eidx;        // edge_index[0]
    const int* dst = eidx + EE;   // edge_index[1]

    float *Xp, *Qp, *Kp, *Vp;
    cudaGetSymbolAddress((void**)&Xp, g_X);
    cudaGetSymbolAddress((void**)&Qp, g_Q);
    cudaGetSymbolAddress((void**)&Kp, g_K);
    cudaGetSymbolAddress((void**)&Vp, g_V);

    zero_cnt_kernel<<<(NN + 255) / 256, 256>>>();
    build_x_kernel<<<(NN * TT + 255) / 256, 256>>>(phys, emb);

    int gemm_blocks = (NN + 63) / 64;
    gemm_kernel<<<gemm_blocks, 256>>>(Xp, TT, Wq, bq, Qp);
    gemm_kernel<<<gemm_blocks, 256>>>(Xp, TT, Wk, bk, Kp);
    gemm_kernel<<<gemm_blocks, 256>>>(emb, HH, Wv, bv, Vp);

    edge_score_kernel<<<EE / 8, 256>>>(src, dst);

    scanA_kernel<<<25, 256>>>();
    scanB_kernel<<<1, 32>>>();
    scanC_kernel<<<25, 256>>>();
    scatter_kernel<<<(EE + 255) / 256, 256>>>(dst);

    aggregate_kernel<<<(NN + 7) / 8, 256>>>(src);

    gemm_ln_kernel<<<gemm_blocks, 256>>>(Wo, bo, emb, gamma, beta, out);
}

// round 5
// speedup vs baseline: 1.1014x; 1.1014x over previous
#include <cuda_runtime.h>
#include <math.h>

#define NN 100000
#define EE 1600000
#define HH 128
#define PP 10
#define TT 138              // PP + HH
#define SCALE 0.08838834764831845f   // 1/sqrt(128)

// ---------------- scratch (static __device__, no allocs) ----------------
__device__ float g_X[NN * TT];      // concat(physics, emb)
__device__ float g_Q[NN * HH];
__device__ float g_K[NN * HH];
__device__ float g_V[NN * HH];
__device__ float g_exps[EE];        // only used by rare deg>32 path
__device__ float g_agg[NN * HH];
__device__ int   g_cnt[NN];
__device__ int   g_off[NN];
__device__ int   g_perm[EE];        // holds SRC node id, sorted by dst
__device__ int   g_bsum[32];

// ---------------- f32x2 packed helpers ----------------
__device__ __forceinline__ unsigned long long pack2(float x, float y) {
    unsigned long long r;
    asm("mov.b64 %0, {%1, %2};" : "=l"(r) : "f"(x), "f"(y));
    return r;
}
__device__ __forceinline__ void unpack2(unsigned long long p, float& x, float& y) {
    asm("mov.b64 {%0, %1}, %2;" : "=f"(x), "=f"(y) : "l"(p));
}
__device__ __forceinline__ unsigned long long fma2(unsigned long long a,
                                                   unsigned long long b,
                                                   unsigned long long c) {
    unsigned long long r;
    asm("fma.rn.f32x2 %0, %1, %2, %3;" : "=l"(r) : "l"(a), "l"(b), "l"(c));
    return r;
}

// ---------------- init ----------------
__global__ void zero_cnt_kernel() {
    int i = blockIdx.x * blockDim.x + threadIdx.x;
    if (i < NN) g_cnt[i] = 0;
}

__global__ void build_x_kernel(const float* __restrict__ phys,
                               const float* __restrict__ emb) {
    int idx = blockIdx.x * blockDim.x + threadIdx.x;
    if (idx >= NN * TT) return;
    int n = idx / TT;
    int c = idx - n * TT;
    g_X[idx] = (c < PP) ? phys[n * PP + c] : emb[n * HH + (c - PP)];
}

// ---------------- fp32 GEMM (packed f32x2): C = A[N,Kdim] @ W + bias ----
// BM=64, BN=128, BK=8, 256 threads; microtile 8 rows x 4 cols, rows paired.
__global__ void __launch_bounds__(256) gemm_kernel(
    const float* __restrict__ A, int Kdim,
    const float* __restrict__ W, const float* __restrict__ bias,
    float* __restrict__ C)
{
    __shared__ __align__(16) float As[8][64];
    __shared__ __align__(16) float Ws[8][128];

    int tid = threadIdx.x;
    int tx = tid & 31;          // col group (4 cols)
    int ty = tid >> 5;          // row group (8 rows)
    int blockM = blockIdx.x * 64;

    unsigned long long cp[4][4];   // [row-pair][col], pair = rows (2p,2p+1)
#pragma unroll
    for (int p = 0; p < 4; p++)
#pragma unroll
        for (int j = 0; j < 4; j++) cp[p][j] = 0ull;

    int am = (tid * 2) >> 3;    // 0..63
    int ak = (tid * 2) & 7;     // 0,2,4,6
    int gm = blockM + am;
    int wk = tid >> 5;          // 0..7
    int wn = (tid & 31) * 4;

    for (int kk = 0; kk < Kdim; kk += 8) {
        float a0 = 0.f, a1 = 0.f;
        if (gm < NN) {
            if (kk + ak < Kdim)     a0 = A[gm * Kdim + kk + ak];
            if (kk + ak + 1 < Kdim) a1 = A[gm * Kdim + kk + ak + 1];
        }
        As[ak][am]     = a0;
        As[ak + 1][am] = a1;

        float4 w = make_float4(0.f, 0.f, 0.f, 0.f);
        if (kk + wk < Kdim) w = *(const float4*)&W[(kk + wk) * HH + wn];
        *(float4*)&Ws[wk][wn] = w;
        __syncthreads();

#pragma unroll
        for (int k = 0; k < 8; k++) {
            float4 b = *(const float4*)&Ws[k][tx * 4];
            unsigned long long b0 = pack2(b.x, b.x);
            unsigned long long b1 = pack2(b.y, b.y);
            unsigned long long b2 = pack2(b.z, b.z);
            unsigned long long b3 = pack2(b.w, b.w);
            const unsigned long long* ap =
                (const unsigned long long*)&As[k][ty * 8];
#pragma unroll
            for (int p = 0; p < 4; p++) {
                unsigned long long a = ap[p];
                cp[p][0] = fma2(a, b0, cp[p][0]);
                cp[p][1] = fma2(a, b1, cp[p][1]);
                cp[p][2] = fma2(a, b2, cp[p][2]);
                cp[p][3] = fma2(a, b3, cp[p][3]);
            }
        }
        __syncthreads();
    }

    float4 bb = *(const float4*)&bias[tx * 4];
    float rows[8][4];
#pragma unroll
    for (int p = 0; p < 4; p++) {
        unpack2(cp[p][0], rows[2*p][0], rows[2*p+1][0]);
        unpack2(cp[p][1], rows[2*p][1], rows[2*p+1][1]);
        unpack2(cp[p][2], rows[2*p][2], rows[2*p+1][2]);
        unpack2(cp[p][3], rows[2*p][3], rows[2*p+1][3]);
    }
#pragma unroll
    for (int i = 0; i < 8; i++) {
        int m = blockM + ty * 8 + i;
        if (m < NN) {
            float4 o = make_float4(rows[i][0] + bb.x, rows[i][1] + bb.y,
                                   rows[i][2] + bb.z, rows[i][3] + bb.w);
            *(float4*)&C[m * HH + tx * 4] = o;
        }
    }
}

// ---------------- histogram of dst ----------------
__global__ void __launch_bounds__(256) hist_kernel(const int* __restrict__ dst) {
    int e = blockIdx.x * blockDim.x + threadIdx.x;
    if (e < EE) atomicAdd(&g_cnt[dst[e]], 1);
}

// ---------------- exclusive scan of g_cnt -> g_off (3 kernels) ----------
__global__ void __launch_bounds__(256) scanA_kernel() {
    __shared__ int wsumI[8];
    int base = blockIdx.x * 4096;
    int t = threadIdx.x;
    int idx0 = base + t * 16;
    int vals[16];
    int s = 0;
#pragma unroll
    for (int j = 0; j < 16; j++) {
        int idx = idx0 + j;
        int v = (idx < NN) ? g_cnt[idx] : 0;
        vals[j] = s;
        s += v;
    }
    int lane = t & 31, wid = t >> 5;
    int incl = s;
#pragma unroll
    for (int o = 1; o < 32; o <<= 1) {
        int v = __shfl_up_sync(0xffffffffu, incl, o);
        if (lane >= o) incl += v;
    }
    if (lane == 31) wsumI[wid] = incl;
    __syncthreads();
    if (wid == 0) {
        int w = (lane < 8) ? wsumI[lane] : 0;
#pragma unroll
        for (int o = 1; o < 8; o <<= 1) {
            int v = __shfl_up_sync(0xffffffffu, w, o);
            if (lane >= o) w += v;
        }
        if (lane < 8) wsumI[lane] = w;
    }
    __syncthreads();
    int texcl = (incl - s) + (wid > 0 ? wsumI[wid - 1] : 0);
#pragma unroll
    for (int j = 0; j < 16; j++) {
        int idx = idx0 + j;
        if (idx < NN) g_off[idx] = texcl + vals[j];
    }
    if (t == 0) g_bsum[blockIdx.x] = wsumI[7];
}

__global__ void scanB_kernel() {
    if (threadIdx.x == 0) {
        int s = 0;
#pragma unroll
        for (int i = 0; i < 25; i++) { int v = g_bsum[i]; g_bsum[i] = s; s += v; }
    }
}

__global__ void __launch_bounds__(256) scanC_kernel() {
    int add = g_bsum[blockIdx.x];
    int idx0 = blockIdx.x * 4096 + threadIdx.x * 16;
#pragma unroll
    for (int j = 0; j < 16; j++) {
        int idx = idx0 + j;
        if (idx < NN) g_off[idx] += add;
    }
}

// ---------------- scatter SRC ids into CSR slots (mutates g_off) --------
// afterwards: segment(n) = [ (n==0?0:g_off[n-1]) , g_off[n] )
__global__ void __launch_bounds__(256) scatter_kernel(const int* __restrict__ src,
                                                      const int* __restrict__ dst) {
    int e = blockIdx.x * blockDim.x + threadIdx.x;
    if (e >= EE) return;
    int d = dst[e];
    int p = atomicAdd(&g_off[d], 1);
    g_perm[p] = src[e];
}

// ---------------- fused per-node: scores + softmax + aggregation --------
// one warp per node; lane-per-edge dot (MLP=32 K-row gathers in flight)
__global__ void __launch_bounds__(256) node_attn_kernel() {
    int n = blockIdx.x * 8 + (threadIdx.x >> 5);
    if (n >= NN) return;
    int lane = threadIdx.x & 31;
    int end = g_off[n];
    int start = (n == 0) ? 0 : g_off[n - 1];
    int deg = end - start;

    float4 acc = make_float4(0.f, 0.f, 0.f, 0.f);

    if (deg > 0) {
        float4 q = *(const float4*)&g_Q[(size_t)n * HH + lane * 4];

        if (deg <= 32) {
            // ---- fast path: everything stays in registers ----
            int s = (lane < deg) ? g_perm[start + lane] : g_perm[start];
            const float4* Krow = (const float4*)&g_K[(size_t)s * HH];
            float dot = 0.f;
#pragma unroll
            for (int j = 0; j < 32; j++) {
                float qx = __shfl_sync(0xffffffffu, q.x, j);
                float qy = __shfl_sync(0xffffffffu, q.y, j);
                float qz = __shfl_sync(0xffffffffu, q.z, j);
                float qw = __shfl_sync(0xffffffffu, q.w, j);
                float4 kv = Krow[j];
                dot += qx * kv.x + qy * kv.y + qz * kv.z + qw * kv.w;
            }
            float w = (lane < deg) ? expf(dot * SCALE) : 0.f;
            float den = w;
#pragma unroll
            for (int o = 16; o > 0; o >>= 1)
                den += __shfl_xor_sync(0xffffffffu, den, o);
            w *= 1.f / (den + 1e-8f);
            for (int j = 0; j < deg; j++) {
                float wj = __shfl_sync(0xffffffffu, w, j);
                int   sj = __shfl_sync(0xffffffffu, s, j);
                float4 v = *(const float4*)&g_V[(size_t)sj * HH + lane * 4];
                acc.x += wj * v.x; acc.y += wj * v.y;
                acc.z += wj * v.z; acc.w += wj * v.w;
            }
        } else {
            // ---- general path (rare): stage scores through g_exps ----
            float den = 0.f;
            for (int base = start; base < end; base += 32) {
                int i = base + lane;
                bool val = (i < end);
                int s = val ? g_perm[i] : g_perm[start];
                const float4* Krow = (const float4*)&g_K[(size_t)s * HH];
                float dot = 0.f;
#pragma unroll
                for (int j = 0; j < 32; j++) {
                    float qx = __shfl_sync(0xffffffffu, q.x, j);
                    float qy = __shfl_sync(0xffffffffu, q.y, j);
                    float qz = __shfl_sync(0xffffffffu, q.z, j);
                    float qw = __shfl_sync(0xffffffffu, q.w, j);
                    float4 kv = Krow[j];
                    dot += qx * kv.x + qy * kv.y + qz * kv.z + qw * kv.w;
                }
                float w = val ? expf(dot * SCALE) : 0.f;
                if (val) g_exps[i] = w;
                den += w;
            }
#pragma unroll
            for (int o = 16; o > 0; o >>= 1)
                den += __shfl_xor_sync(0xffffffffu, den, o);
            float invden = 1.f / (den + 1e-8f);
            for (int base = start; base < end; base += 32) {
                int i = base + lane;
                bool val = (i < end);
                float w = val ? g_exps[i] * invden : 0.f;
                int   s = val ? g_perm[i] : 0;
                int cnt = min(32, end - base);
                for (int j = 0; j < cnt; j++) {
                    float wj = __shfl_sync(0xffffffffu, w, j);
                    int   sj = __shfl_sync(0xffffffffu, s, j);
                    float4 v = *(const float4*)&g_V[(size_t)sj * HH + lane * 4];
                    acc.x += wj * v.x; acc.y += wj * v.y;
                    acc.z += wj * v.z; acc.w += wj * v.w;
                }
            }
        }
    }
    *(float4*)&g_agg[(size_t)n * HH + lane * 4] = acc;
}

// ---------------- O-GEMM + residual + LayerNorm fused (packed) ----------
__global__ void __launch_bounds__(256) gemm_ln_kernel(
    const float* __restrict__ W, const float* __restrict__ bias,
    const float* __restrict__ emb, const float* __restrict__ gamma,
    const float* __restrict__ beta, float* __restrict__ out)
{
    __shared__ __align__(16) float As[8][64];
    __shared__ __align__(16) float Ws[8][128];

    int tid = threadIdx.x;
    int tx = tid & 31;
    int ty = tid >> 5;
    int blockM = blockIdx.x * 64;

    unsigned long long cp[4][4];
#pragma unroll
    for (int p = 0; p < 4; p++)
#pragma unroll
        for (int j = 0; j < 4; j++) cp[p][j] = 0ull;

    int am = (tid * 2) >> 3;
    int ak = (tid * 2) & 7;
    int gm = blockM + am;
    int wk = tid >> 5;
    int wn = (tid & 31) * 4;

    for (int kk = 0; kk < HH; kk += 8) {
        float a0 = 0.f, a1 = 0.f;
        if (gm < NN) {
            a0 = g_agg[gm * HH + kk + ak];
            a1 = g_agg[gm * HH + kk + ak + 1];
        }
        As[ak][am]     = a0;
        As[ak + 1][am] = a1;
        float4 w = *(const float4*)&W[(kk + wk) * HH + wn];
        *(float4*)&Ws[wk][wn] = w;
        __syncthreads();
#pragma unroll
        for (int k = 0; k < 8; k++) {
            float4 b = *(const float4*)&Ws[k][tx * 4];
            unsigned long long b0 = pack2(b.x, b.x);
            unsigned long long b1 = pack2(b.y, b.y);
            unsigned long long b2 = pack2(b.z, b.z);
            unsigned long long b3 = pack2(b.w, b.w);
            const unsigned long long* ap =
                (const unsigned long long*)&As[k][ty * 8];
#pragma unroll
            for (int p = 0; p < 4; p++) {
                unsigned long long a = ap[p];
                cp[p][0] = fma2(a, b0, cp[p][0]);
                cp[p][1] = fma2(a, b1, cp[p][1]);
                cp[p][2] = fma2(a, b2, cp[p][2]);
                cp[p][3] = fma2(a, b3, cp[p][3]);
            }
        }
        __syncthreads();
    }

    float4 bb  = *(const float4*)&bias[tx * 4];
    float4 gm4 = *(const float4*)&gamma[tx * 4];
    float4 bt4 = *(const float4*)&beta[tx * 4];

    float rows[8][4];
#pragma unroll
    for (int p = 0; p < 4; p++) {
        unpack2(cp[p][0], rows[2*p][0], rows[2*p+1][0]);
        unpack2(cp[p][1], rows[2*p][1], rows[2*p+1][1]);
        unpack2(cp[p][2], rows[2*p][2], rows[2*p+1][2]);
        unpack2(cp[p][3], rows[2*p][3], rows[2*p+1][3]);
    }

#pragma unroll
    for (int i = 0; i < 8; i++) {
        int m = blockM + ty * 8 + i;
        if (m < NN) {
            float4 e = *(const float4*)&emb[m * HH + tx * 4];
            float x0 = rows[i][0] + bb.x + e.x;
            float x1 = rows[i][1] + bb.y + e.y;
            float x2 = rows[i][2] + bb.z + e.z;
            float x3 = rows[i][3] + bb.w + e.w;
            float s = x0 + x1 + x2 + x3;
            float q = x0 * x0 + x1 * x1 + x2 * x2 + x3 * x3;
#pragma unroll
            for (int o = 16; o > 0; o >>= 1) {
                s += __shfl_xor_sync(0xffffffffu, s, o);
                q += __shfl_xor_sync(0xffffffffu, q, o);
            }
            float mean = s * (1.f / 128.f);
            float var  = q * (1.f / 128.f) - mean * mean;
            float r = rsqrtf(var + 1e-5f);
            float4 o4 = make_float4(gm4.x * (x0 - mean) * r + bt4.x,
                                    gm4.y * (x1 - mean) * r + bt4.y,
                                    gm4.z * (x2 - mean) * r + bt4.z,
                                    gm4.w * (x3 - mean) * r + bt4.w);
            *(float4*)&out[m * HH + tx * 4] = o4;
        }
    }
}

// ---------------- launch ----------------
extern "C" void kernel_launch(void* const* d_in, const int* in_sizes, int n_in,
                              void* d_out, int out_size)
{
    const float* phys  = (const float*)d_in[0];
    const float* emb   = (const float*)d_in[1];
    const int*   eidx  = (const int*)  d_in[2];
    const float* Wq    = (const float*)d_in[3];
    const float* bq    = (const float*)d_in[4];
    const float* Wk    = (const float*)d_in[5];
    const float* bk    = (const float*)d_in[6];
    const float* Wv    = (const float*)d_in[7];
    const float* bv    = (const float*)d_in[8];
    const float* Wo    = (const float*)d_in[9];
    const float* bo    = (const float*)d_in[10];
    const float* gamma = (const float*)d_in[11];
    const float* beta  = (const float*)d_in[12];
    float* out = (float*)d_out;

    const int* src = eidx;        // edge_index[0]
    const int* dst = eidx + EE;   // edge_index[1]

    float *Xp, *Qp, *Kp, *Vp;
    cudaGetSymbolAddress((void**)&Xp, g_X);
    cudaGetSymbolAddress((void**)&Qp, g_Q);
    cudaGetSymbolAddress((void**)&Kp, g_K);
    cudaGetSymbolAddress((void**)&Vp, g_V);

    zero_cnt_kernel<<<(NN + 255) / 256, 256>>>();
    build_x_kernel<<<(NN * TT + 255) / 256, 256>>>(phys, emb);

    int gemm_blocks = (NN + 63) / 64;
    gemm_kernel<<<gemm_blocks, 256>>>(Xp, TT, Wq, bq, Qp);
    gemm_kernel<<<gemm_blocks, 256>>>(Xp, TT, Wk, bk, Kp);
    gemm_kernel<<<gemm_blocks, 256>>>(emb, HH, Wv, bv, Vp);

    hist_kernel<<<(EE + 255) / 256, 256>>>(dst);
    scanA_kernel<<<25, 256>>>();
    scanB_kernel<<<1, 32>>>();
    scanC_kernel<<<25, 256>>>();
    scatter_kernel<<<(EE + 255) / 256, 256>>>(src, dst);

    node_attn_kernel<<<(NN + 7) / 8, 256>>>();

    gemm_ln_kernel<<<gemm_blocks, 256>>>(Wo, bo, emb, gamma, beta, out);
}

// round 10
// speedup vs baseline: 1.1516x; 1.0455x over previous
#include <cuda_runtime.h>
#include <stdint.h>
#include <math.h>

#define NN 100000
#define NPAD 100096          // 782 tiles of 128
#define NTILES 782
#define EE 1600000
#define HH 128
#define PP 10
#define TT 138               // PP + HH
#define KTOT 144             // K padded (6 chunks of 24)
#define SCALE 0.08838834764831845f   // 1/sqrt(128)

// ---------------- scratch (static __device__, no allocs) ----------------
__device__ float g_X[NPAD * KTOT];  // concat(physics, emb), zero-padded
__device__ float g_Q[NN * HH];
__device__ float g_K[NN * HH];
__device__ float g_V[NN * HH];
__device__ float g_exps[EE];        // only used by rare deg>32 path
__device__ float g_agg[NN * HH];
__device__ int   g_cnt[NN];
__device__ int   g_off[NN];
__device__ int   g_perm[EE];        // holds SRC node id, sorted by dst
__device__ int   g_bsum[32];

// ---------------- helpers ----------------
__device__ __forceinline__ uint32_t f2u(float x) { return __float_as_uint(x); }

__device__ __forceinline__ float tf32_round(float x) {
    uint32_t r;
    asm("cvt.rna.tf32.f32 %0, %1;" : "=r"(r) : "f"(x));
    return __uint_as_float(r);
}

#define MMA_TF32(d, a, b) \
    asm volatile( \
        "mma.sync.aligned.m16n8k8.row.col.f32.tf32.tf32.f32 " \
        "{%0,%1,%2,%3}, {%4,%5,%6,%7}, {%8,%9}, {%0,%1,%2,%3};" \
        : "+f"((d)[0]), "+f"((d)[1]), "+f"((d)[2]), "+f"((d)[3]) \
        : "r"((a)[0]), "r"((a)[1]), "r"((a)[2]), "r"((a)[3]), \
          "r"((b)[0]), "r"((b)[1]))

// f32x2 packed helpers (for gemm_ln)
__device__ __forceinline__ unsigned long long pack2(float x, float y) {
    unsigned long long r;
    asm("mov.b64 %0, {%1, %2};" : "=l"(r) : "f"(x), "f"(y));
    return r;
}
__device__ __forceinline__ void unpack2(unsigned long long p, float& x, float& y) {
    asm("mov.b64 {%0, %1}, %2;" : "=f"(x), "=f"(y) : "l"(p));
}
__device__ __forceinline__ unsigned long long fma2(unsigned long long a,
                                                   unsigned long long b,
                                                   unsigned long long c) {
    unsigned long long r;
    asm("fma.rn.f32x2 %0, %1, %2, %3;" : "=l"(r) : "l"(a), "l"(b), "l"(c));
    return r;
}

// ---------------- prep kernels ----------------
__global__ void zero_cnt_kernel() {
    int i = blockIdx.x * blockDim.x + threadIdx.x;
    if (i < NN) g_cnt[i] = 0;
}

// concat(physics, emb) padded to 144 cols, NPAD rows (zeros outside)
__global__ void __launch_bounds__(256) build_x_kernel(
    const float* __restrict__ phys, const float* __restrict__ emb)
{
    int idx = blockIdx.x * blockDim.x + threadIdx.x;
    if (idx >= NPAD * KTOT) return;
    int n = idx / KTOT;
    int c = idx - n * KTOT;
    float v = 0.f;
    if (n < NN) {
        if (c < PP) v = phys[n * PP + c];
        else if (c < TT) v = emb[n * HH + (c - PP)];
    }
    g_X[idx] = v;
}

// ---------------- tf32 mma GEMM: C[128,128] = A @ W + bias -------------
// BM=128, BN=128, BK=24 (6 chunks over KTOT=144), 256 threads, 8 warps,
// warp tile 32x64 = 2x8 m16n8k8 tiles; hi/lo tf32 3-pass for fp32 accuracy.
// smem float offsets: Ah 0, Al 3200, Bh 6400, Bl 9664, bias 12928 (13056 tot)
#define SM_AH 0
#define SM_AL 3200
#define SM_BH 6400
#define SM_BL 9664
#define SM_BIAS 12928
#define SM_FLOATS 13056

__global__ void __launch_bounds__(256, 2) mma_gemm_kernel(
    const float* __restrict__ A, int ldA, int nrowsA, int kmaxB,
    const float* __restrict__ W, const float* __restrict__ bias,
    float* __restrict__ C)
{
    extern __shared__ float sm[];
    float* Ah = sm + SM_AH;
    float* Al = sm + SM_AL;
    float* Bh = sm + SM_BH;
    float* Bl = sm + SM_BL;
    float* bsm = sm + SM_BIAS;

    int tid = threadIdx.x;
    if (tid < 128) bsm[tid] = bias[tid];

    int mbase = blockIdx.x * 128;
    int w = tid >> 5, lane = tid & 31;
    int wm = w & 3, wn = w >> 2;
    int gr = lane >> 2, lc = lane & 3;

    float d[2][8][4];
#pragma unroll
    for (int mt = 0; mt < 2; mt++)
#pragma unroll
        for (int nt = 0; nt < 8; nt++)
#pragma unroll
            for (int j = 0; j < 4; j++) d[mt][nt][j] = 0.f;

    // hoisted load coordinates (3 float4 each for A and B per chunk)
    int ar[3], akq[3]; bool arok[3];
    int bk[3], bcq[3];
#pragma unroll
    for (int i = 0; i < 3; i++) {
        int fa = tid + i * 256;
        ar[i] = fa / 6;
        akq[i] = (fa % 6) * 4;
        arok[i] = (mbase + ar[i]) < nrowsA;
        bk[i] = fa >> 5;
        bcq[i] = (fa & 31) << 2;
    }

    for (int ch = 0; ch < 6; ch++) {
        int kk = ch * 24;
        float4 av[3], bv[3];
#pragma unroll
        for (int i = 0; i < 3; i++) {
            bool aok = arok[i] && (kk + akq[i] < ldA);
            av[i] = aok ? *(const float4*)&A[(size_t)(mbase + ar[i]) * ldA + kk + akq[i]]
                        : make_float4(0.f, 0.f, 0.f, 0.f);
            int kg = kk + bk[i];
            bv[i] = (kg < kmaxB) ? *(const float4*)&W[kg * 128 + bcq[i]]
                                 : make_float4(0.f, 0.f, 0.f, 0.f);
        }
        __syncthreads();   // previous chunk's compute done before overwrite
#pragma unroll
        for (int i = 0; i < 3; i++) {
            // A: scalar stores, layout [row][25]
            int ab = ar[i] * 25 + akq[i];
            float x;
            x = av[i].x; { float h = tf32_round(x); Ah[ab+0] = h; Al[ab+0] = tf32_round(x - h); }
            x = av[i].y; { float h = tf32_round(x); Ah[ab+1] = h; Al[ab+1] = tf32_round(x - h); }
            x = av[i].z; { float h = tf32_round(x); Ah[ab+2] = h; Al[ab+2] = tf32_round(x - h); }
            x = av[i].w; { float h = tf32_round(x); Ah[ab+3] = h; Al[ab+3] = tf32_round(x - h); }
            // B: vector stores, layout [k][136]
            int bb = bk[i] * 136 + bcq[i];
            float4 h4, l4;
            h4.x = tf32_round(bv[i].x); l4.x = tf32_round(bv[i].x - h4.x);
            h4.y = tf32_round(bv[i].y); l4.y = tf32_round(bv[i].y - h4.y);
            h4.z = tf32_round(bv[i].z); l4.z = tf32_round(bv[i].z - h4.z);
            h4.w = tf32_round(bv[i].w); l4.w = tf32_round(bv[i].w - h4.w);
            *(float4*)&Bh[bb] = h4;
            *(float4*)&Bl[bb] = l4;
        }
        __syncthreads();

#pragma unroll
        for (int ks = 0; ks < 3; ks++) {
            int kb = ks * 8;
            uint32_t ah[2][4], bh[8][2];
#pragma unroll
            for (int mt = 0; mt < 2; mt++) {
                int base = (wm * 32 + mt * 16 + gr) * 25 + kb + lc;
                ah[mt][0] = f2u(Ah[base]);
                ah[mt][1] = f2u(Ah[base + 8 * 25]);
                ah[mt][2] = f2u(Ah[base + 4]);
                ah[mt][3] = f2u(Ah[base + 8 * 25 + 4]);
            }
#pragma unroll
            for (int nt = 0; nt < 8; nt++) {
                int b0 = (kb + lc) * 136 + wn * 64 + nt * 8 + gr;
                bh[nt][0] = f2u(Bh[b0]);
                bh[nt][1] = f2u(Bh[b0 + 4 * 136]);
            }
            // pass hh
#pragma unroll
            for (int mt = 0; mt < 2; mt++)
#pragma unroll
                for (int nt = 0; nt < 8; nt++) MMA_TF32(d[mt][nt], ah[mt], bh[nt]);
            // pass lh (Al x Bh)
            {
                uint32_t al[2][4];
#pragma unroll
                for (int mt = 0; mt < 2; mt++) {
                    int base = (wm * 32 + mt * 16 + gr) * 25 + kb + lc;
                    al[mt][0] = f2u(Al[base]);
                    al[mt][1] = f2u(Al[base + 8 * 25]);
                    al[mt][2] = f2u(Al[base + 4]);
                    al[mt][3] = f2u(Al[base + 8 * 25 + 4]);
                }
#pragma unroll
                for (int mt = 0; mt < 2; mt++)
#pragma unroll
                    for (int nt = 0; nt < 8; nt++) MMA_TF32(d[mt][nt], al[mt], bh[nt]);
            }
            // pass hl (Ah x Bl)
            {
                uint32_t bl[8][2];
#pragma unroll
                for (int nt = 0; nt < 8; nt++) {
                    int b0 = (kb + lc) * 136 + wn * 64 + nt * 8 + gr;
                    bl[nt][0] = f2u(Bl[b0]);
                    bl[nt][1] = f2u(Bl[b0 + 4 * 136]);
                }
#pragma unroll
                for (int mt = 0; mt < 2; mt++)
#pragma unroll
                    for (int nt = 0; nt < 8; nt++) MMA_TF32(d[mt][nt], ah[mt], bl[nt]);
            }
        }
    }

    // epilogue: bias add, write fp32 (predicated on m < NN)
#pragma unroll
    for (int mt = 0; mt < 2; mt++) {
        int r0 = mbase + wm * 32 + mt * 16 + gr;
#pragma unroll
        for (int nt = 0; nt < 8; nt++) {
            int col = wn * 64 + nt * 8 + lc * 2;
            float b0 = bsm[col], b1 = bsm[col + 1];
            if (r0 < NN) {
                float2 o = make_float2(d[mt][nt][0] + b0, d[mt][nt][1] + b1);
                *(float2*)&C[(size_t)r0 * HH + col] = o;
            }
            if (r0 + 8 < NN) {
                float2 o = make_float2(d[mt][nt][2] + b0, d[mt][nt][3] + b1);
                *(float2*)&C[(size_t)(r0 + 8) * HH + col] = o;
            }
        }
    }
}

// ---------------- histogram of dst ----------------
__global__ void __launch_bounds__(256) hist_kernel(const int* __restrict__ dst) {
    int e = blockIdx.x * blockDim.x + threadIdx.x;
    if (e < EE) atomicAdd(&g_cnt[dst[e]], 1);
}

// ---------------- exclusive scan of g_cnt -> g_off (3 kernels) ----------
__global__ void __launch_bounds__(256) scanA_kernel() {
    __shared__ int wsumI[8];
    int base = blockIdx.x * 4096;
    int t = threadIdx.x;
    int idx0 = base + t * 16;
    int vals[16];
    int s = 0;
#pragma unroll
    for (int j = 0; j < 16; j++) {
        int idx = idx0 + j;
        int v = (idx < NN) ? g_cnt[idx] : 0;
        vals[j] = s;
        s += v;
    }
    int lane = t & 31, wid = t >> 5;
    int incl = s;
#pragma unroll
    for (int o = 1; o < 32; o <<= 1) {
        int v = __shfl_up_sync(0xffffffffu, incl, o);
        if (lane >= o) incl += v;
    }
    if (lane == 31) wsumI[wid] = incl;
    __syncthreads();
    if (wid == 0) {
        int w = (lane < 8) ? wsumI[lane] : 0;
#pragma unroll
        for (int o = 1; o < 8; o <<= 1) {
            int v = __shfl_up_sync(0xffffffffu, w, o);
            if (lane >= o) w += v;
        }
        if (lane < 8) wsumI[lane] = w;
    }
    __syncthreads();
    int texcl = (incl - s) + (wid > 0 ? wsumI[wid - 1] : 0);
#pragma unroll
    for (int j = 0; j < 16; j++) {
        int idx = idx0 + j;
        if (idx < NN) g_off[idx] = texcl + vals[j];
    }
    if (t == 0) g_bsum[blockIdx.x] = wsumI[7];
}

__global__ void scanB_kernel() {
    if (threadIdx.x == 0) {
        int s = 0;
#pragma unroll
        for (int i = 0; i < 25; i++) { int v = g_bsum[i]; g_bsum[i] = s; s += v; }
    }
}

__global__ void __launch_bounds__(256) scanC_kernel() {
    int add = g_bsum[blockIdx.x];
    int idx0 = blockIdx.x * 4096 + threadIdx.x * 16;
#pragma unroll
    for (int j = 0; j < 16; j++) {
        int idx = idx0 + j;
        if (idx < NN) g_off[idx] += add;
    }
}

// ---------------- scatter SRC ids into CSR slots (mutates g_off) --------
__global__ void __launch_bounds__(256) scatter_kernel(const int* __restrict__ src,
                                                      const int* __restrict__ dst) {
    int e = blockIdx.x * blockDim.x + threadIdx.x;
    if (e >= EE) return;
    int d = dst[e];
    int p = atomicAdd(&g_off[d], 1);
    g_perm[p] = src[e];
}

// ---------------- fused per-node: scores + softmax + aggregation --------
__global__ void __launch_bounds__(256) node_attn_kernel() {
    int n = blockIdx.x * 8 + (threadIdx.x >> 5);
    if (n >= NN) return;
    int lane = threadIdx.x & 31;
    int end = g_off[n];
    int start = (n == 0) ? 0 : g_off[n - 1];
    int deg = end - start;

    float4 acc = make_float4(0.f, 0.f, 0.f, 0.f);

    if (deg > 0) {
        float4 q = *(const float4*)&g_Q[(size_t)n * HH + lane * 4];

        if (deg <= 32) {
            int s = (lane < deg) ? g_perm[start + lane] : g_perm[start];
            const float4* Krow = (const float4*)&g_K[(size_t)s * HH];
            float dot = 0.f;
#pragma unroll
            for (int j = 0; j < 32; j++) {
                float qx = __shfl_sync(0xffffffffu, q.x, j);
                float qy = __shfl_sync(0xffffffffu, q.y, j);
                float qz = __shfl_sync(0xffffffffu, q.z, j);
                float qw = __shfl_sync(0xffffffffu, q.w, j);
                float4 kv = Krow[j];
                dot += qx * kv.x + qy * kv.y + qz * kv.z + qw * kv.w;
            }
            float w = (lane < deg) ? expf(dot * SCALE) : 0.f;
            float den = w;
#pragma unroll
            for (int o = 16; o > 0; o >>= 1)
                den += __shfl_xor_sync(0xffffffffu, den, o);
            w *= 1.f / (den + 1e-8f);
            for (int j = 0; j < deg; j++) {
                float wj = __shfl_sync(0xffffffffu, w, j);
                int   sj = __shfl_sync(0xffffffffu, s, j);
                float4 v = *(const float4*)&g_V[(size_t)sj * HH + lane * 4];
                acc.x += wj * v.x; acc.y += wj * v.y;
                acc.z += wj * v.z; acc.w += wj * v.w;
            }
        } else {
            float den = 0.f;
            for (int base = start; base < end; base += 32) {
                int i = base + lane;
                bool val = (i < end);
                int s = val ? g_perm[i] : g_perm[start];
                const float4* Krow = (const float4*)&g_K[(size_t)s * HH];
                float dot = 0.f;
#pragma unroll
                for (int j = 0; j < 32; j++) {
                    float qx = __shfl_sync(0xffffffffu, q.x, j);
                    float qy = __shfl_sync(0xffffffffu, q.y, j);
                    float qz = __shfl_sync(0xffffffffu, q.z, j);
                    float qw = __shfl_sync(0xffffffffu, q.w, j);
                    float4 kv = Krow[j];
                    dot += qx * kv.x + qy * kv.y + qz * kv.z + qw * kv.w;
                }
                float w = val ? expf(dot * SCALE) : 0.f;
                if (val) g_exps[i] = w;
                den += w;
            }
#pragma unroll
            for (int o = 16; o > 0; o >>= 1)
                den += __shfl_xor_sync(0xffffffffu, den, o);
            float invden = 1.f / (den + 1e-8f);
            for (int base = start; base < end; base += 32) {
                int i = base + lane;
                bool val = (i < end);
                float w = val ? g_exps[i] * invden : 0.f;
                int   s = val ? g_perm[i] : 0;
                int cnt = min(32, end - base);
                for (int j = 0; j < cnt; j++) {
                    float wj = __shfl_sync(0xffffffffu, w, j);
                    int   sj = __shfl_sync(0xffffffffu, s, j);
                    float4 v = *(const float4*)&g_V[(size_t)sj * HH + lane * 4];
                    acc.x += wj * v.x; acc.y += wj * v.y;
                    acc.z += wj * v.z; acc.w += wj * v.w;
                }
            }
        }
    }
    *(float4*)&g_agg[(size_t)n * HH + lane * 4] = acc;
}

// ---------------- O-GEMM + residual + LayerNorm fused (packed f32x2) ----
__global__ void __launch_bounds__(256) gemm_ln_kernel(
    const float* __restrict__ W, const float* __restrict__ bias,
    const float* __restrict__ emb, const float* __restrict__ gamma,
    const float* __restrict__ beta, float* __restrict__ out)
{
    __shared__ __align__(16) float As[8][64];
    __shared__ __align__(16) float Ws[8][128];

    int tid = threadIdx.x;
    int tx = tid & 31;
    int ty = tid >> 5;
    int blockM = blockIdx.x * 64;

    unsigned long long cp[4][4];
#pragma unroll
    for (int p = 0; p < 4; p++)
#pragma unroll
        for (int j = 0; j < 4; j++) cp[p][j] = 0ull;

    int am = (tid * 2) >> 3;
    int ak = (tid * 2) & 7;
    int gm = blockM + am;
    int wk = tid >> 5;
    int wn = (tid & 31) * 4;

    for (int kk = 0; kk < HH; kk += 8) {
        float a0 = 0.f, a1 = 0.f;
        if (gm < NN) {
            a0 = g_agg[gm * HH + kk + ak];
            a1 = g_agg[gm * HH + kk + ak + 1];
        }
        As[ak][am]     = a0;
        As[ak + 1][am] = a1;
        float4 w = *(const float4*)&W[(kk + wk) * HH + wn];
        *(float4*)&Ws[wk][wn] = w;
        __syncthreads();
#pragma unroll
        for (int k = 0; k < 8; k++) {
            float4 b = *(const float4*)&Ws[k][tx * 4];
            unsigned long long b0 = pack2(b.x, b.x);
            unsigned long long b1 = pack2(b.y, b.y);
            unsigned long long b2 = pack2(b.z, b.z);
            unsigned long long b3 = pack2(b.w, b.w);
            const unsigned long long* ap =
                (const unsigned long long*)&As[k][ty * 8];
#pragma unroll
            for (int p = 0; p < 4; p++) {
                unsigned long long a = ap[p];
                cp[p][0] = fma2(a, b0, cp[p][0]);
                cp[p][1] = fma2(a, b1, cp[p][1]);
                cp[p][2] = fma2(a, b2, cp[p][2]);
                cp[p][3] = fma2(a, b3, cp[p][3]);
            }
        }
        __syncthreads();
    }

    float4 bb  = *(const float4*)&bias[tx * 4];
    float4 gm4 = *(const float4*)&gamma[tx * 4];
    float4 bt4 = *(const float4*)&beta[tx * 4];

    float rows[8][4];
#pragma unroll
    for (int p = 0; p < 4; p++) {
        unpack2(cp[p][0], rows[2*p][0], rows[2*p+1][0]);
        unpack2(cp[p][1], rows[2*p][1], rows[2*p+1][1]);
        unpack2(cp[p][2], rows[2*p][2], rows[2*p+1][2]);
        unpack2(cp[p][3], rows[2*p][3], rows[2*p+1][3]);
    }

#pragma unroll
    for (int i = 0; i < 8; i++) {
        int m = blockM + ty * 8 + i;
        if (m < NN) {
            float4 e = *(const float4*)&emb[m * HH + tx * 4];
            float x0 = rows[i][0] + bb.x + e.x;
            float x1 = rows[i][1] + bb.y + e.y;
            float x2 = rows[i][2] + bb.z + e.z;
            float x3 = rows[i][3] + bb.w + e.w;
            float s = x0 + x1 + x2 + x3;
            float q = x0 * x0 + x1 * x1 + x2 * x2 + x3 * x3;
#pragma unroll
            for (int o = 16; o > 0; o >>= 1) {
                s += __shfl_xor_sync(0xffffffffu, s, o);
                q += __shfl_xor_sync(0xffffffffu, q, o);
            }
            float mean = s * (1.f / 128.f);
            float var  = q * (1.f / 128.f) - mean * mean;
            float r = rsqrtf(var + 1e-5f);
            float4 o4 = make_float4(gm4.x * (x0 - mean) * r + bt4.x,
                                    gm4.y * (x1 - mean) * r + bt4.y,
                                    gm4.z * (x2 - mean) * r + bt4.z,
                                    gm4.w * (x3 - mean) * r + bt4.w);
            *(float4*)&out[m * HH + tx * 4] = o4;
        }
    }
}

// ---------------- launch ----------------
extern "C" void kernel_launch(void* const* d_in, const int* in_sizes, int n_in,
                              void* d_out, int out_size)
{
    const float* phys  = (const float*)d_in[0];
    const float* emb   = (const float*)d_in[1];
    const int*   eidx  = (const int*)  d_in[2];
    const float* Wq    = (const float*)d_in[3];
    const float* bq    = (const float*)d_in[4];
    const float* Wk    = (const float*)d_in[5];
    const float* bk    = (const float*)d_in[6];
    const float* Wv    = (const float*)d_in[7];
    const float* bv    = (const float*)d_in[8];
    const float* Wo    = (const float*)d_in[9];
    const float* bo    = (const float*)d_in[10];
    const float* gamma = (const float*)d_in[11];
    const float* beta  = (const float*)d_in[12];
    float* out = (float*)d_out;

    const int* src = eidx;        // edge_index[0]
    const int* dst = eidx + EE;   // edge_index[1]

    float *Xp, *Qp, *Kp, *Vp;
    cudaGetSymbolAddress((void**)&Xp, g_X);
    cudaGetSymbolAddress((void**)&Qp, g_Q);
    cudaGetSymbolAddress((void**)&Kp, g_K);
    cudaGetSymbolAddress((void**)&Vp, g_V);

    const int SMEM_BYTES = SM_FLOATS * 4;   // 52224
    cudaFuncSetAttribute(mma_gemm_kernel,
                         cudaFuncAttributeMaxDynamicSharedMemorySize, SMEM_BYTES);

    zero_cnt_kernel<<<(NN + 255) / 256, 256>>>();
    build_x_kernel<<<(NPAD * KTOT + 255) / 256, 256>>>(phys, emb);

    // Q, K: A = g_X (ldA=144, rows NPAD valid/zeroed), B valid k < 138
    mma_gemm_kernel<<<NTILES, 256, SMEM_BYTES>>>(Xp, KTOT, NPAD, TT, Wq, bq, Qp);
    mma_gemm_kernel<<<NTILES, 256, SMEM_BYTES>>>(Xp, KTOT, NPAD, TT, Wk, bk, Kp);
    // V: A = emb (ldA=128, rows NN), B valid k < 128
    mma_gemm_kernel<<<NTILES, 256, SMEM_BYTES>>>(emb, HH, NN, HH, Wv, bv, Vp);

    hist_kernel<<<(EE + 255) / 256, 256>>>(dst);
    scanA_kernel<<<25, 256>>>();
    scanB_kernel<<<1, 32>>>();
    scanC_kernel<<<25, 256>>>();
    scatter_kernel<<<(EE + 255) / 256, 256>>>(src, dst);

    node_attn_kernel<<<(NN + 7) / 8, 256>>>();

    gemm_ln_kernel<<<(NN + 63) / 64, 256>>>(Wo, bo, emb, gamma, beta, out);
}

// round 11
// speedup vs baseline: 1.2183x; 1.0579x over previous
#include <cuda_runtime.h>
#include <cuda_bf16.h>
#include <stdint.h>
#include <math.h>

#define NN 100000
#define NPAD 100096          // 782 tiles of 128
#define NTILES 782
#define EE 1600000
#define HH 128
#define PP 10
#define TT 138               // PP + HH
#define KTOT 144             // K padded (6 chunks of 24)
#define SCALE 0.08838834764831845f   // 1/sqrt(128)

// ---------------- scratch (static __device__, no allocs) ----------------
__device__ float g_X[NPAD * KTOT];  // concat(physics, emb), zero-padded
__device__ float g_Q[NN * HH];
__device__ __nv_bfloat16 g_Kb[NN * HH];   // K in bf16 (gather-only consumer)
__device__ __nv_bfloat16 g_Vb[NN * HH];   // V in bf16 (gather-only consumer)
__device__ float g_exps[EE];        // only used by rare deg>32 path
__device__ float g_agg[NN * HH];
__device__ int   g_cnt[NN];
__device__ int   g_off[NN];
__device__ int   g_perm[EE];        // holds SRC node id, sorted by dst
__device__ int   g_bsum[32];

// ---------------- helpers ----------------
__device__ __forceinline__ uint32_t f2u(float x) { return __float_as_uint(x); }

__device__ __forceinline__ float tf32_round(float x) {
    uint32_t r;
    asm("cvt.rna.tf32.f32 %0, %1;" : "=r"(r) : "f"(x));
    return __uint_as_float(r);
}

// unpack bf16x2 word -> two floats (elem e = low half, elem e+1 = high half)
__device__ __forceinline__ float2 bf2f2(uint32_t p) {
    return make_float2(__uint_as_float(p << 16),
                       __uint_as_float(p & 0xffff0000u));
}

#define MMA_TF32(d, a, b) \
    asm volatile( \
        "mma.sync.aligned.m16n8k8.row.col.f32.tf32.tf32.f32 " \
        "{%0,%1,%2,%3}, {%4,%5,%6,%7}, {%8,%9}, {%0,%1,%2,%3};" \
        : "+f"((d)[0]), "+f"((d)[1]), "+f"((d)[2]), "+f"((d)[3]) \
        : "r"((a)[0]), "r"((a)[1]), "r"((a)[2]), "r"((a)[3]), \
          "r"((b)[0]), "r"((b)[1]))

// f32x2 packed helpers (for gemm_ln)
__device__ __forceinline__ unsigned long long pack2(float x, float y) {
    unsigned long long r;
    asm("mov.b64 %0, {%1, %2};" : "=l"(r) : "f"(x), "f"(y));
    return r;
}
__device__ __forceinline__ void unpack2(unsigned long long p, float& x, float& y) {
    asm("mov.b64 {%0, %1}, %2;" : "=f"(x), "=f"(y) : "l"(p));
}
__device__ __forceinline__ unsigned long long fma2(unsigned long long a,
                                                   unsigned long long b,
                                                   unsigned long long c) {
    unsigned long long r;
    asm("fma.rn.f32x2 %0, %1, %2, %3;" : "=l"(r) : "l"(a), "l"(b), "l"(c));
    return r;
}

// ---------------- prep kernels ----------------
__global__ void zero_cnt_kernel() {
    int i = blockIdx.x * blockDim.x + threadIdx.x;
    if (i < NN) g_cnt[i] = 0;
}

// concat(physics, emb) padded to 144 cols, NPAD rows (zeros outside)
__global__ void __launch_bounds__(256) build_x_kernel(
    const float* __restrict__ phys, const float* __restrict__ emb)
{
    int idx = blockIdx.x * blockDim.x + threadIdx.x;
    if (idx >= NPAD * KTOT) return;
    int n = idx / KTOT;
    int c = idx - n * KTOT;
    float v = 0.f;
    if (n < NN) {
        if (c < PP) v = phys[n * PP + c];
        else if (c < TT) v = emb[n * HH + (c - PP)];
    }
    g_X[idx] = v;
}

// ---------------- tf32 mma GEMM: C[128,128] = A @ W + bias -------------
// BM=128, BN=128, BK=24 (6 chunks over KTOT=144), 256 threads, 8 warps,
// warp tile 32x64 = 2x8 m16n8k8 tiles; hi/lo tf32 3-pass for fp32 accuracy.
// bf16out: pack column pairs to bf16x2 and store 4B (for K / V outputs).
#define SM_AH 0
#define SM_AL 3200
#define SM_BH 6400
#define SM_BL 9664
#define SM_BIAS 12928
#define SM_FLOATS 13056

__global__ void __launch_bounds__(256, 2) mma_gemm_kernel(
    const float* __restrict__ A, int ldA, int nrowsA, int kmaxB,
    const float* __restrict__ W, const float* __restrict__ bias,
    void* __restrict__ Cv, int bf16out)
{
    extern __shared__ float sm[];
    float* Ah = sm + SM_AH;
    float* Al = sm + SM_AL;
    float* Bh = sm + SM_BH;
    float* Bl = sm + SM_BL;
    float* bsm = sm + SM_BIAS;

    int tid = threadIdx.x;
    if (tid < 128) bsm[tid] = bias[tid];

    int mbase = blockIdx.x * 128;
    int w = tid >> 5, lane = tid & 31;
    int wm = w & 3, wn = w >> 2;
    int gr = lane >> 2, lc = lane & 3;

    float d[2][8][4];
#pragma unroll
    for (int mt = 0; mt < 2; mt++)
#pragma unroll
        for (int nt = 0; nt < 8; nt++)
#pragma unroll
            for (int j = 0; j < 4; j++) d[mt][nt][j] = 0.f;

    int ar[3], akq[3]; bool arok[3];
    int bk[3], bcq[3];
#pragma unroll
    for (int i = 0; i < 3; i++) {
        int fa = tid + i * 256;
        ar[i] = fa / 6;
        akq[i] = (fa % 6) * 4;
        arok[i] = (mbase + ar[i]) < nrowsA;
        bk[i] = fa >> 5;
        bcq[i] = (fa & 31) << 2;
    }

    for (int ch = 0; ch < 6; ch++) {
        int kk = ch * 24;
        float4 av[3], bv[3];
#pragma unroll
        for (int i = 0; i < 3; i++) {
            bool aok = arok[i] && (kk + akq[i] < ldA);
            av[i] = aok ? *(const float4*)&A[(size_t)(mbase + ar[i]) * ldA + kk + akq[i]]
                        : make_float4(0.f, 0.f, 0.f, 0.f);
            int kg = kk + bk[i];
            bv[i] = (kg < kmaxB) ? *(const float4*)&W[kg * 128 + bcq[i]]
                                 : make_float4(0.f, 0.f, 0.f, 0.f);
        }
        __syncthreads();
#pragma unroll
        for (int i = 0; i < 3; i++) {
            int ab = ar[i] * 25 + akq[i];
            float x;
            x = av[i].x; { float h = tf32_round(x); Ah[ab+0] = h; Al[ab+0] = tf32_round(x - h); }
            x = av[i].y; { float h = tf32_round(x); Ah[ab+1] = h; Al[ab+1] = tf32_round(x - h); }
            x = av[i].z; { float h = tf32_round(x); Ah[ab+2] = h; Al[ab+2] = tf32_round(x - h); }
            x = av[i].w; { float h = tf32_round(x); Ah[ab+3] = h; Al[ab+3] = tf32_round(x - h); }
            int bb = bk[i] * 136 + bcq[i];
            float4 h4, l4;
            h4.x = tf32_round(bv[i].x); l4.x = tf32_round(bv[i].x - h4.x);
            h4.y = tf32_round(bv[i].y); l4.y = tf32_round(bv[i].y - h4.y);
            h4.z = tf32_round(bv[i].z); l4.z = tf32_round(bv[i].z - h4.z);
            h4.w = tf32_round(bv[i].w); l4.w = tf32_round(bv[i].w - h4.w);
            *(float4*)&Bh[bb] = h4;
            *(float4*)&Bl[bb] = l4;
        }
        __syncthreads();

#pragma unroll
        for (int ks = 0; ks < 3; ks++) {
            int kb = ks * 8;
            uint32_t ah[2][4], bh[8][2];
#pragma unroll
            for (int mt = 0; mt < 2; mt++) {
                int base = (wm * 32 + mt * 16 + gr) * 25 + kb + lc;
                ah[mt][0] = f2u(Ah[base]);
                ah[mt][1] = f2u(Ah[base + 8 * 25]);
                ah[mt][2] = f2u(Ah[base + 4]);
                ah[mt][3] = f2u(Ah[base + 8 * 25 + 4]);
            }
#pragma unroll
            for (int nt = 0; nt < 8; nt++) {
                int b0 = (kb + lc) * 136 + wn * 64 + nt * 8 + gr;
                bh[nt][0] = f2u(Bh[b0]);
                bh[nt][1] = f2u(Bh[b0 + 4 * 136]);
            }
#pragma unroll
            for (int mt = 0; mt < 2; mt++)
#pragma unroll
                for (int nt = 0; nt < 8; nt++) MMA_TF32(d[mt][nt], ah[mt], bh[nt]);
            {
                uint32_t al[2][4];
#pragma unroll
                for (int mt = 0; mt < 2; mt++) {
                    int base = (wm * 32 + mt * 16 + gr) * 25 + kb + lc;
                    al[mt][0] = f2u(Al[base]);
                    al[mt][1] = f2u(Al[base + 8 * 25]);
                    al[mt][2] = f2u(Al[base + 4]);
                    al[mt][3] = f2u(Al[base + 8 * 25 + 4]);
                }
#pragma unroll
                for (int mt = 0; mt < 2; mt++)
#pragma unroll
                    for (int nt = 0; nt < 8; nt++) MMA_TF32(d[mt][nt], al[mt], bh[nt]);
            }
            {
                uint32_t bl[8][2];
#pragma unroll
                for (int nt = 0; nt < 8; nt++) {
                    int b0 = (kb + lc) * 136 + wn * 64 + nt * 8 + gr;
                    bl[nt][0] = f2u(Bl[b0]);
                    bl[nt][1] = f2u(Bl[b0 + 4 * 136]);
                }
#pragma unroll
                for (int mt = 0; mt < 2; mt++)
#pragma unroll
                    for (int nt = 0; nt < 8; nt++) MMA_TF32(d[mt][nt], ah[mt], bl[nt]);
            }
        }
    }

    // epilogue: bias add, write fp32 or bf16 (predicated on m < NN)
    if (!bf16out) {
        float* C = (float*)Cv;
#pragma unroll
        for (int mt = 0; mt < 2; mt++) {
            int r0 = mbase + wm * 32 + mt * 16 + gr;
#pragma unroll
            for (int nt = 0; nt < 8; nt++) {
                int col = wn * 64 + nt * 8 + lc * 2;
                float b0 = bsm[col], b1 = bsm[col + 1];
                if (r0 < NN) {
                    float2 o = make_float2(d[mt][nt][0] + b0, d[mt][nt][1] + b1);
                    *(float2*)&C[(size_t)r0 * HH + col] = o;
                }
                if (r0 + 8 < NN) {
                    float2 o = make_float2(d[mt][nt][2] + b0, d[mt][nt][3] + b1);
                    *(float2*)&C[(size_t)(r0 + 8) * HH + col] = o;
                }
            }
        }
    } else {
        __nv_bfloat16* C = (__nv_bfloat16*)Cv;
#pragma unroll
        for (int mt = 0; mt < 2; mt++) {
            int r0 = mbase + wm * 32 + mt * 16 + gr;
#pragma unroll
            for (int nt = 0; nt < 8; nt++) {
                int col = wn * 64 + nt * 8 + lc * 2;
                float b0 = bsm[col], b1 = bsm[col + 1];
                if (r0 < NN) {
                    __nv_bfloat162 h = __float22bfloat162_rn(
                        make_float2(d[mt][nt][0] + b0, d[mt][nt][1] + b1));
                    *(__nv_bfloat162*)&C[(size_t)r0 * HH + col] = h;
                }
                if (r0 + 8 < NN) {
                    __nv_bfloat162 h = __float22bfloat162_rn(
                        make_float2(d[mt][nt][2] + b0, d[mt][nt][3] + b1));
                    *(__nv_bfloat162*)&C[(size_t)(r0 + 8) * HH + col] = h;
                }
            }
        }
    }
}

// ---------------- histogram of dst ----------------
__global__ void __launch_bounds__(256) hist_kernel(const int* __restrict__ dst) {
    int e = blockIdx.x * blockDim.x + threadIdx.x;
    if (e < EE) atomicAdd(&g_cnt[dst[e]], 1);
}

// ---------------- exclusive scan of g_cnt -> g_off (3 kernels) ----------
__global__ void __launch_bounds__(256) scanA_kernel() {
    __shared__ int wsumI[8];
    int base = blockIdx.x * 4096;
    int t = threadIdx.x;
    int idx0 = base + t * 16;
    int vals[16];
    int s = 0;
#pragma unroll
    for (int j = 0; j < 16; j++) {
        int idx = idx0 + j;
        int v = (idx < NN) ? g_cnt[idx] : 0;
        vals[j] = s;
        s += v;
    }
    int lane = t & 31, wid = t >> 5;
    int incl = s;
#pragma unroll
    for (int o = 1; o < 32; o <<= 1) {
        int v = __shfl_up_sync(0xffffffffu, incl, o);
        if (lane >= o) incl += v;
    }
    if (lane == 31) wsumI[wid] = incl;
    __syncthreads();
    if (wid == 0) {
        int w = (lane < 8) ? wsumI[lane] : 0;
#pragma unroll
        for (int o = 1; o < 8; o <<= 1) {
            int v = __shfl_up_sync(0xffffffffu, w, o);
            if (lane >= o) w += v;
        }
        if (lane < 8) wsumI[lane] = w;
    }
    __syncthreads();
    int texcl = (incl - s) + (wid > 0 ? wsumI[wid - 1] : 0);
#pragma unroll
    for (int j = 0; j < 16; j++) {
        int idx = idx0 + j;
        if (idx < NN) g_off[idx] = texcl + vals[j];
    }
    if (t == 0) g_bsum[blockIdx.x] = wsumI[7];
}

__global__ void scanB_kernel() {
    if (threadIdx.x == 0) {
        int s = 0;
#pragma unroll
        for (int i = 0; i < 25; i++) { int v = g_bsum[i]; g_bsum[i] = s; s += v; }
    }
}

__global__ void __launch_bounds__(256) scanC_kernel() {
    int add = g_bsum[blockIdx.x];
    int idx0 = blockIdx.x * 4096 + threadIdx.x * 16;
#pragma unroll
    for (int j = 0; j < 16; j++) {
        int idx = idx0 + j;
        if (idx < NN) g_off[idx] += add;
    }
}

// ---------------- scatter SRC ids into CSR slots (mutates g_off) --------
__global__ void __launch_bounds__(256) scatter_kernel(const int* __restrict__ src,
                                                      const int* __restrict__ dst) {
    int e = blockIdx.x * blockDim.x + threadIdx.x;
    if (e >= EE) return;
    int d = dst[e];
    int p = atomicAdd(&g_off[d], 1);
    g_perm[p] = src[e];
}

// ---------------- fused per-node: scores + softmax + aggregation --------
// one warp per node; K/V gathered as bf16 (half the bytes of fp32)
__global__ void __launch_bounds__(256) node_attn_kernel() {
    int n = blockIdx.x * 8 + (threadIdx.x >> 5);
    if (n >= NN) return;
    int lane = threadIdx.x & 31;
    int end = g_off[n];
    int start = (n == 0) ? 0 : g_off[n - 1];
    int deg = end - start;

    float4 acc = make_float4(0.f, 0.f, 0.f, 0.f);

    if (deg > 0) {
        float4 q = *(const float4*)&g_Q[(size_t)n * HH + lane * 4];

        if (deg <= 32) {
            int s = (lane < deg) ? g_perm[start + lane] : g_perm[start];
            const uint2* Krow = (const uint2*)(g_Kb + (size_t)s * HH);
            float dot = 0.f;
#pragma unroll
            for (int j = 0; j < 32; j++) {
                float qx = __shfl_sync(0xffffffffu, q.x, j);
                float qy = __shfl_sync(0xffffffffu, q.y, j);
                float qz = __shfl_sync(0xffffffffu, q.z, j);
                float qw = __shfl_sync(0xffffffffu, q.w, j);
                uint2 kp = Krow[j];
                float2 k01 = bf2f2(kp.x), k23 = bf2f2(kp.y);
                dot += qx * k01.x + qy * k01.y + qz * k23.x + qw * k23.y;
            }
            float w = (lane < deg) ? expf(dot * SCALE) : 0.f;
            float den = w;
#pragma unroll
            for (int o = 16; o > 0; o >>= 1)
                den += __shfl_xor_sync(0xffffffffu, den, o);
            w *= 1.f / (den + 1e-8f);
            for (int j = 0; j < deg; j++) {
                float wj = __shfl_sync(0xffffffffu, w, j);
                int   sj = __shfl_sync(0xffffffffu, s, j);
                uint2 vp = *(const uint2*)(g_Vb + (size_t)sj * HH + lane * 4);
                float2 v01 = bf2f2(vp.x), v23 = bf2f2(vp.y);
                acc.x += wj * v01.x; acc.y += wj * v01.y;
                acc.z += wj * v23.x; acc.w += wj * v23.y;
            }
        } else {
            float den = 0.f;
            for (int base = start; base < end; base += 32) {
                int i = base + lane;
                bool val = (i < end);
                int s = val ? g_perm[i] : g_perm[start];
                const uint2* Krow = (const uint2*)(g_Kb + (size_t)s * HH);
                float dot = 0.f;
#pragma unroll
                for (int j = 0; j < 32; j++) {
                    float qx = __shfl_sync(0xffffffffu, q.x, j);
                    float qy = __shfl_sync(0xffffffffu, q.y, j);
                    float qz = __shfl_sync(0xffffffffu, q.z, j);
                    float qw = __shfl_sync(0xffffffffu, q.w, j);
                    uint2 kp = Krow[j];
                    float2 k01 = bf2f2(kp.x), k23 = bf2f2(kp.y);
                    dot += qx * k01.x + qy * k01.y + qz * k23.x + qw * k23.y;
                }
                float w = val ? expf(dot * SCALE) : 0.f;
                if (val) g_exps[i] = w;
                den += w;
            }
#pragma unroll
            for (int o = 16; o > 0; o >>= 1)
                den += __shfl_xor_sync(0xffffffffu, den, o);
            float invden = 1.f / (den + 1e-8f);
            for (int base = start; base < end; base += 32) {
                int i = base + lane;
                bool val = (i < end);
                float w = val ? g_exps[i] * invden : 0.f;
                int   s = val ? g_perm[i] : 0;
                int cnt = min(32, end - base);
                for (int j = 0; j < cnt; j++) {
                    float wj = __shfl_sync(0xffffffffu, w, j);
                    int   sj = __shfl_sync(0xffffffffu, s, j);
                    uint2 vp = *(const uint2*)(g_Vb + (size_t)sj * HH + lane * 4);
                    float2 v01 = bf2f2(vp.x), v23 = bf2f2(vp.y);
                    acc.x += wj * v01.x; acc.y += wj * v01.y;
                    acc.z += wj * v23.x; acc.w += wj * v23.y;
                }
            }
        }
    }
    *(float4*)&g_agg[(size_t)n * HH + lane * 4] = acc;
}

// ---------------- O-GEMM + residual + LayerNorm fused (packed f32x2) ----
__global__ void __launch_bounds__(256) gemm_ln_kernel(
    const float* __restrict__ W, const float* __restrict__ bias,
    const float* __restrict__ emb, const float* __restrict__ gamma,
    const float* __restrict__ beta, float* __restrict__ out)
{
    __shared__ __align__(16) float As[8][64];
    __shared__ __align__(16) float Ws[8][128];

    int tid = threadIdx.x;
    int tx = tid & 31;
    int ty = tid >> 5;
    int blockM = blockIdx.x * 64;

    unsigned long long cp[4][4];
#pragma unroll
    for (int p = 0; p < 4; p++)
#pragma unroll
        for (int j = 0; j < 4; j++) cp[p][j] = 0ull;

    int am = (tid * 2) >> 3;
    int ak = (tid * 2) & 7;
    int gm = blockM + am;
    int wk = tid >> 5;
    int wn = (tid & 31) * 4;

    for (int kk = 0; kk < HH; kk += 8) {
        float a0 = 0.f, a1 = 0.f;
        if (gm < NN) {
            a0 = g_agg[gm * HH + kk + ak];
            a1 = g_agg[gm * HH + kk + ak + 1];
        }
        As[ak][am]     = a0;
        As[ak + 1][am] = a1;
        float4 w = *(const float4*)&W[(kk + wk) * HH + wn];
        *(float4*)&Ws[wk][wn] = w;
        __syncthreads();
#pragma unroll
        for (int k = 0; k < 8; k++) {
            float4 b = *(const float4*)&Ws[k][tx * 4];
            unsigned long long b0 = pack2(b.x, b.x);
            unsigned long long b1 = pack2(b.y, b.y);
            unsigned long long b2 = pack2(b.z, b.z);
            unsigned long long b3 = pack2(b.w, b.w);
            const unsigned long long* ap =
                (const unsigned long long*)&As[k][ty * 8];
#pragma unroll
            for (int p = 0; p < 4; p++) {
                unsigned long long a = ap[p];
                cp[p][0] = fma2(a, b0, cp[p][0]);
                cp[p][1] = fma2(a, b1, cp[p][1]);
                cp[p][2] = fma2(a, b2, cp[p][2]);
                cp[p][3] = fma2(a, b3, cp[p][3]);
            }
        }
        __syncthreads();
    }

    float4 bb  = *(const float4*)&bias[tx * 4];
    float4 gm4 = *(const float4*)&gamma[tx * 4];
    float4 bt4 = *(const float4*)&beta[tx * 4];

    float rows[8][4];
#pragma unroll
    for (int p = 0; p < 4; p++) {
        unpack2(cp[p][0], rows[2*p][0], rows[2*p+1][0]);
        unpack2(cp[p][1], rows[2*p][1], rows[2*p+1][1]);
        unpack2(cp[p][2], rows[2*p][2], rows[2*p+1][2]);
        unpack2(cp[p][3], rows[2*p][3], rows[2*p+1][3]);
    }

#pragma unroll
    for (int i = 0; i < 8; i++) {
        int m = blockM + ty * 8 + i;
        if (m < NN) {
            float4 e = *(const float4*)&emb[m * HH + tx * 4];
            float x0 = rows[i][0] + bb.x + e.x;
            float x1 = rows[i][1] + bb.y + e.y;
            float x2 = rows[i][2] + bb.z + e.z;
            float x3 = rows[i][3] + bb.w + e.w;
            float s = x0 + x1 + x2 + x3;
            float q = x0 * x0 + x1 * x1 + x2 * x2 + x3 * x3;
#pragma unroll
            for (int o = 16; o > 0; o >>= 1) {
                s += __shfl_xor_sync(0xffffffffu, s, o);
                q += __shfl_xor_sync(0xffffffffu, q, o);
            }
            float mean = s * (1.f / 128.f);
            float var  = q * (1.f / 128.f) - mean * mean;
            float r = rsqrtf(var + 1e-5f);
            float4 o4 = make_float4(gm4.x * (x0 - mean) * r + bt4.x,
                                    gm4.y * (x1 - mean) * r + bt4.y,
                                    gm4.z * (x2 - mean) * r + bt4.z,
                                    gm4.w * (x3 - mean) * r + bt4.w);
            *(float4*)&out[m * HH + tx * 4] = o4;
        }
    }
}

// ---------------- launch ----------------
extern "C" void kernel_launch(void* const* d_in, const int* in_sizes, int n_in,
                              void* d_out, int out_size)
{
    const float* phys  = (const float*)d_in[0];
    const float* emb   = (const float*)d_in[1];
    const int*   eidx  = (const int*)  d_in[2];
    const float* Wq    = (const float*)d_in[3];
    const float* bq    = (const float*)d_in[4];
    const float* Wk    = (const float*)d_in[5];
    const float* bk    = (const float*)d_in[6];
    const float* Wv    = (const float*)d_in[7];
    const float* bv    = (const float*)d_in[8];
    const float* Wo    = (const float*)d_in[9];
    const float* bo    = (const float*)d_in[10];
    const float* gamma = (const float*)d_in[11];
    const float* beta  = (const float*)d_in[12];
    float* out = (float*)d_out;

    const int* src = eidx;        // edge_index[0]
    const int* dst = eidx + EE;   // edge_index[1]

    float *Xp, *Qp;
    __nv_bfloat16 *Kbp, *Vbp;
    cudaGetSymbolAddress((void**)&Xp, g_X);
    cudaGetSymbolAddress((void**)&Qp, g_Q);
    cudaGetSymbolAddress((void**)&Kbp, g_Kb);
    cudaGetSymbolAddress((void**)&Vbp, g_Vb);

    const int SMEM_BYTES = SM_FLOATS * 4;   // 52224
    cudaFuncSetAttribute(mma_gemm_kernel,
                         cudaFuncAttributeMaxDynamicSharedMemorySize, SMEM_BYTES);

    zero_cnt_kernel<<<(NN + 255) / 256, 256>>>();
    build_x_kernel<<<(NPAD * KTOT + 255) / 256, 256>>>(phys, emb);

    // Q: fp32 out; K, V: bf16 out (only consumed by edge gathers)
    mma_gemm_kernel<<<NTILES, 256, SMEM_BYTES>>>(Xp, KTOT, NPAD, TT, Wq, bq, Qp, 0);
    mma_gemm_kernel<<<NTILES, 256, SMEM_BYTES>>>(Xp, KTOT, NPAD, TT, Wk, bk, Kbp, 1);
    mma_gemm_kernel<<<NTILES, 256, SMEM_BYTES>>>(emb, HH, NN, HH, Wv, bv, Vbp, 1);

    hist_kernel<<<(EE + 255) / 256, 256>>>(dst);
    scanA_kernel<<<25, 256>>>();
    scanB_kernel<<<1, 32>>>();
    scanC_kernel<<<25, 256>>>();
    scatter_kernel<<<(EE + 255) / 256, 256>>>(src, dst);

    node_attn_kernel<<<(NN + 7) / 8, 256>>>();

    gemm_ln_kernel<<<(NN + 63) / 64, 256>>>(Wo, bo, emb, gamma, beta, out);
}

// round 12
// speedup vs baseline: 1.4183x; 1.1642x over previous
#include <cuda_runtime.h>
#include <cuda_bf16.h>
#include <stdint.h>
#include <math.h>

#define NN 100000
#define NPAD 100096          // 782 tiles of 128
#define NTILES 782
#define EE 1600000
#define HH 128
#define PP 10
#define TT 138               // PP + HH
#define KTOT 144             // K padded (6 chunks of 24)
#define SCALE 0.08838834764831845f   // 1/sqrt(128)

// ---------------- scratch (static __device__, no allocs) ----------------
__device__ float g_X[NPAD * KTOT];  // concat(physics, emb), zero-padded
__device__ float g_Q[NN * HH];
__device__ __nv_bfloat16 g_Kb[NN * HH];   // K in bf16 (gather-only consumer)
__device__ __nv_bfloat16 g_Vb[NN * HH];   // V in bf16 (gather-only consumer)
__device__ float g_exps[EE];        // only used by rare deg>32 path
__device__ float g_agg[NN * HH];
__device__ int   g_cnt[NN];
__device__ int   g_off[NN];
__device__ int   g_perm[EE];        // holds SRC node id, sorted by dst
__device__ int   g_bsum[32];

// ---------------- helpers ----------------
__device__ __forceinline__ uint32_t f2u(float x) { return __float_as_uint(x); }

__device__ __forceinline__ float tf32_round(float x) {
    uint32_t r;
    asm("cvt.rna.tf32.f32 %0, %1;" : "=r"(r) : "f"(x));
    return __uint_as_float(r);
}

// unpack bf16x2 word -> two floats (elem e = low half, elem e+1 = high half)
__device__ __forceinline__ float2 bf2f2(uint32_t p) {
    return make_float2(__uint_as_float(p << 16),
                       __uint_as_float(p & 0xffff0000u));
}

#define MMA_TF32(d, a, b) \
    asm volatile( \
        "mma.sync.aligned.m16n8k8.row.col.f32.tf32.tf32.f32 " \
        "{%0,%1,%2,%3}, {%4,%5,%6,%7}, {%8,%9}, {%0,%1,%2,%3};" \
        : "+f"((d)[0]), "+f"((d)[1]), "+f"((d)[2]), "+f"((d)[3]) \
        : "r"((a)[0]), "r"((a)[1]), "r"((a)[2]), "r"((a)[3]), \
          "r"((b)[0]), "r"((b)[1]))

// f32x2 packed helpers (for gemm_ln)
__device__ __forceinline__ unsigned long long pack2(float x, float y) {
    unsigned long long r;
    asm("mov.b64 %0, {%1, %2};" : "=l"(r) : "f"(x), "f"(y));
    return r;
}
__device__ __forceinline__ void unpack2(unsigned long long p, float& x, float& y) {
    asm("mov.b64 {%0, %1}, %2;" : "=f"(x), "=f"(y) : "l"(p));
}
__device__ __forceinline__ unsigned long long fma2(unsigned long long a,
                                                   unsigned long long b,
                                                   unsigned long long c) {
    unsigned long long r;
    asm("fma.rn.f32x2 %0, %1, %2, %3;" : "=l"(r) : "l"(a), "l"(b), "l"(c));
    return r;
}

// ---------------- prep kernels ----------------
__global__ void zero_cnt_kernel() {
    int i = blockIdx.x * blockDim.x + threadIdx.x;
    if (i < NN) g_cnt[i] = 0;
}

// concat(physics, emb) padded to 144 cols, NPAD rows (zeros outside)
__global__ void __launch_bounds__(256) build_x_kernel(
    const float* __restrict__ phys, const float* __restrict__ emb)
{
    int idx = blockIdx.x * blockDim.x + threadIdx.x;
    if (idx >= NPAD * KTOT) return;
    int n = idx / KTOT;
    int c = idx - n * KTOT;
    float v = 0.f;
    if (n < NN) {
        if (c < PP) v = phys[n * PP + c];
        else if (c < TT) v = emb[n * HH + (c - PP)];
    }
    g_X[idx] = v;
}

// ---------------- tf32 mma GEMM: C[128,128] = A @ W + bias -------------
// BM=128, BN=128, BK=24 (6 chunks over KTOT=144), 256 threads, 8 warps,
// warp tile 32x64 = 2x8 m16n8k8 tiles; SINGLE-PASS tf32 (per-term 2^-12,
// below the bf16 output rounding already accepted downstream).
// bf16out: pack column pairs to bf16x2 and store 4B (for K / V outputs).
#define SM_AH 0
#define SM_BH 3200
#define SM_BIAS 6464
#define SM_FLOATS 6592

__global__ void __launch_bounds__(256, 2) mma_gemm_kernel(
    const float* __restrict__ A, int ldA, int nrowsA, int kmaxB,
    const float* __restrict__ W, const float* __restrict__ bias,
    void* __restrict__ Cv, int bf16out)
{
    extern __shared__ float sm[];
    float* Ah = sm + SM_AH;
    float* Bh = sm + SM_BH;
    float* bsm = sm + SM_BIAS;

    int tid = threadIdx.x;
    if (tid < 128) bsm[tid] = bias[tid];

    int mbase = blockIdx.x * 128;
    int w = tid >> 5, lane = tid & 31;
    int wm = w & 3, wn = w >> 2;
    int gr = lane >> 2, lc = lane & 3;

    float d[2][8][4];
#pragma unroll
    for (int mt = 0; mt < 2; mt++)
#pragma unroll
        for (int nt = 0; nt < 8; nt++)
#pragma unroll
            for (int j = 0; j < 4; j++) d[mt][nt][j] = 0.f;

    int ar[3], akq[3]; bool arok[3];
    int bk[3], bcq[3];
#pragma unroll
    for (int i = 0; i < 3; i++) {
        int fa = tid + i * 256;
        ar[i] = fa / 6;
        akq[i] = (fa % 6) * 4;
        arok[i] = (mbase + ar[i]) < nrowsA;
        bk[i] = fa >> 5;
        bcq[i] = (fa & 31) << 2;
    }

    for (int ch = 0; ch < 6; ch++) {
        int kk = ch * 24;
        float4 av[3], bv[3];
#pragma unroll
        for (int i = 0; i < 3; i++) {
            bool aok = arok[i] && (kk + akq[i] < ldA);
            av[i] = aok ? *(const float4*)&A[(size_t)(mbase + ar[i]) * ldA + kk + akq[i]]
                        : make_float4(0.f, 0.f, 0.f, 0.f);
            int kg = kk + bk[i];
            bv[i] = (kg < kmaxB) ? *(const float4*)&W[kg * 128 + bcq[i]]
                                 : make_float4(0.f, 0.f, 0.f, 0.f);
        }
        __syncthreads();
#pragma unroll
        for (int i = 0; i < 3; i++) {
            int ab = ar[i] * 25 + akq[i];
            Ah[ab+0] = tf32_round(av[i].x);
            Ah[ab+1] = tf32_round(av[i].y);
            Ah[ab+2] = tf32_round(av[i].z);
            Ah[ab+3] = tf32_round(av[i].w);
            int bb = bk[i] * 136 + bcq[i];
            float4 h4;
            h4.x = tf32_round(bv[i].x);
            h4.y = tf32_round(bv[i].y);
            h4.z = tf32_round(bv[i].z);
            h4.w = tf32_round(bv[i].w);
            *(float4*)&Bh[bb] = h4;
        }
        __syncthreads();

#pragma unroll
        for (int ks = 0; ks < 3; ks++) {
            int kb = ks * 8;
            uint32_t ah[2][4], bh[8][2];
#pragma unroll
            for (int mt = 0; mt < 2; mt++) {
                int base = (wm * 32 + mt * 16 + gr) * 25 + kb + lc;
                ah[mt][0] = f2u(Ah[base]);
                ah[mt][1] = f2u(Ah[base + 8 * 25]);
                ah[mt][2] = f2u(Ah[base + 4]);
                ah[mt][3] = f2u(Ah[base + 8 * 25 + 4]);
            }
#pragma unroll
            for (int nt = 0; nt < 8; nt++) {
                int b0 = (kb + lc) * 136 + wn * 64 + nt * 8 + gr;
                bh[nt][0] = f2u(Bh[b0]);
                bh[nt][1] = f2u(Bh[b0 + 4 * 136]);
            }
#pragma unroll
            for (int mt = 0; mt < 2; mt++)
#pragma unroll
                for (int nt = 0; nt < 8; nt++) MMA_TF32(d[mt][nt], ah[mt], bh[nt]);
        }
    }

    // epilogue: bias add, write fp32 or bf16 (predicated on m < NN)
    if (!bf16out) {
        float* C = (float*)Cv;
#pragma unroll
        for (int mt = 0; mt < 2; mt++) {
            int r0 = mbase + wm * 32 + mt * 16 + gr;
#pragma unroll
            for (int nt = 0; nt < 8; nt++) {
                int col = wn * 64 + nt * 8 + lc * 2;
                float b0 = bsm[col], b1 = bsm[col + 1];
                if (r0 < NN) {
                    float2 o = make_float2(d[mt][nt][0] + b0, d[mt][nt][1] + b1);
                    *(float2*)&C[(size_t)r0 * HH + col] = o;
                }
                if (r0 + 8 < NN) {
                    float2 o = make_float2(d[mt][nt][2] + b0, d[mt][nt][3] + b1);
                    *(float2*)&C[(size_t)(r0 + 8) * HH + col] = o;
                }
            }
        }
    } else {
        __nv_bfloat16* C = (__nv_bfloat16*)Cv;
#pragma unroll
        for (int mt = 0; mt < 2; mt++) {
            int r0 = mbase + wm * 32 + mt * 16 + gr;
#pragma unroll
            for (int nt = 0; nt < 8; nt++) {
                int col = wn * 64 + nt * 8 + lc * 2;
                float b0 = bsm[col], b1 = bsm[col + 1];
                if (r0 < NN) {
                    __nv_bfloat162 h = __float22bfloat162_rn(
                        make_float2(d[mt][nt][0] + b0, d[mt][nt][1] + b1));
                    *(__nv_bfloat162*)&C[(size_t)r0 * HH + col] = h;
                }
                if (r0 + 8 < NN) {
                    __nv_bfloat162 h = __float22bfloat162_rn(
                        make_float2(d[mt][nt][2] + b0, d[mt][nt][3] + b1));
                    *(__nv_bfloat162*)&C[(size_t)(r0 + 8) * HH + col] = h;
                }
            }
        }
    }
}

// ---------------- histogram of dst ----------------
__global__ void __launch_bounds__(256) hist_kernel(const int* __restrict__ dst) {
    int e = blockIdx.x * blockDim.x + threadIdx.x;
    if (e < EE) atomicAdd(&g_cnt[dst[e]], 1);
}

// ---------------- exclusive scan of g_cnt -> g_off (3 kernels) ----------
__global__ void __launch_bounds__(256) scanA_kernel() {
    __shared__ int wsumI[8];
    int base = blockIdx.x * 4096;
    int t = threadIdx.x;
    int idx0 = base + t * 16;
    int vals[16];
    int s = 0;
#pragma unroll
    for (int j = 0; j < 16; j++) {
        int idx = idx0 + j;
        int v = (idx < NN) ? g_cnt[idx] : 0;
        vals[j] = s;
        s += v;
    }
    int lane = t & 31, wid = t >> 5;
    int incl = s;
#pragma unroll
    for (int o = 1; o < 32; o <<= 1) {
        int v = __shfl_up_sync(0xffffffffu, incl, o);
        if (lane >= o) incl += v;
    }
    if (lane == 31) wsumI[wid] = incl;
    __syncthreads();
    if (wid == 0) {
        int w = (lane < 8) ? wsumI[lane] : 0;
#pragma unroll
        for (int o = 1; o < 8; o <<= 1) {
            int v = __shfl_up_sync(0xffffffffu, w, o);
            if (lane >= o) w += v;
        }
        if (lane < 8) wsumI[lane] = w;
    }
    __syncthreads();
    int texcl = (incl - s) + (wid > 0 ? wsumI[wid - 1] : 0);
#pragma unroll
    for (int j = 0; j < 16; j++) {
        int idx = idx0 + j;
        if (idx < NN) g_off[idx] = texcl + vals[j];
    }
    if (t == 0) g_bsum[blockIdx.x] = wsumI[7];
}

__global__ void scanB_kernel() {
    if (threadIdx.x == 0) {
        int s = 0;
#pragma unroll
        for (int i = 0; i < 25; i++) { int v = g_bsum[i]; g_bsum[i] = s; s += v; }
    }
}

__global__ void __launch_bounds__(256) scanC_kernel() {
    int add = g_bsum[blockIdx.x];
    int idx0 = blockIdx.x * 4096 + threadIdx.x * 16;
#pragma unroll
    for (int j = 0; j < 16; j++) {
        int idx = idx0 + j;
        if (idx < NN) g_off[idx] += add;
    }
}

// ---------------- scatter SRC ids into CSR slots (mutates g_off) --------
__global__ void __launch_bounds__(256) scatter_kernel(const int* __restrict__ src,
                                                      const int* __restrict__ dst) {
    int e = blockIdx.x * blockDim.x + threadIdx.x;
    if (e >= EE) return;
    int d = dst[e];
    int p = atomicAdd(&g_off[d], 1);
    g_perm[p] = src[e];
}

// ---------------- fused per-node: scores + softmax + aggregation --------
// one warp per node; K/V gathered as bf16; V loop in unrolled chunks of 8
// (predicated weights: w==0 beyond deg, addresses always valid) for MLP=8.
__global__ void __launch_bounds__(256) node_attn_kernel() {
    int n = blockIdx.x * 8 + (threadIdx.x >> 5);
    if (n >= NN) return;
    int lane = threadIdx.x & 31;
    int end = g_off[n];
    int start = (n == 0) ? 0 : g_off[n - 1];
    int deg = end - start;

    float4 acc = make_float4(0.f, 0.f, 0.f, 0.f);

    if (deg > 0) {
        float4 q = *(const float4*)&g_Q[(size_t)n * HH + lane * 4];

        if (deg <= 32) {
            int s = (lane < deg) ? g_perm[start + lane] : g_perm[start];
            const uint2* Krow = (const uint2*)(g_Kb + (size_t)s * HH);
            float dot = 0.f;
#pragma unroll
            for (int j = 0; j < 32; j++) {
                float qx = __shfl_sync(0xffffffffu, q.x, j);
                float qy = __shfl_sync(0xffffffffu, q.y, j);
                float qz = __shfl_sync(0xffffffffu, q.z, j);
                float qw = __shfl_sync(0xffffffffu, q.w, j);
                uint2 kp = Krow[j];
                float2 k01 = bf2f2(kp.x), k23 = bf2f2(kp.y);
                dot += qx * k01.x + qy * k01.y + qz * k23.x + qw * k23.y;
            }
            float w = (lane < deg) ? expf(dot * SCALE) : 0.f;
            float den = w;
#pragma unroll
            for (int o = 16; o > 0; o >>= 1)
                den += __shfl_xor_sync(0xffffffffu, den, o);
            w *= 1.f / (den + 1e-8f);
            int nch = (deg + 7) >> 3;
            for (int c = 0; c < nch; c++) {
                int j0 = c * 8;
#pragma unroll
                for (int jj = 0; jj < 8; jj++) {
                    int j = j0 + jj;
                    float wj = __shfl_sync(0xffffffffu, w, j);
                    int   sj = __shfl_sync(0xffffffffu, s, j);
                    uint2 vp = *(const uint2*)(g_Vb + (size_t)sj * HH + lane * 4);
                    float2 v01 = bf2f2(vp.x), v23 = bf2f2(vp.y);
                    acc.x += wj * v01.x; acc.y += wj * v01.y;
                    acc.z += wj * v23.x; acc.w += wj * v23.y;
                }
            }
        } else {
            float den = 0.f;
            for (int base = start; base < end; base += 32) {
                int i = base + lane;
                bool val = (i < end);
                int s = val ? g_perm[i] : g_perm[start];
                const uint2* Krow = (const uint2*)(g_Kb + (size_t)s * HH);
                float dot = 0.f;
#pragma unroll
                for (int j = 0; j < 32; j++) {
                    float qx = __shfl_sync(0xffffffffu, q.x, j);
                    float qy = __shfl_sync(0xffffffffu, q.y, j);
                    float qz = __shfl_sync(0xffffffffu, q.z, j);
                    float qw = __shfl_sync(0xffffffffu, q.w, j);
                    uint2 kp = Krow[j];
                    float2 k01 = bf2f2(kp.x), k23 = bf2f2(kp.y);
                    dot += qx * k01.x + qy * k01.y + qz * k23.x + qw * k23.y;
                }
                float w = val ? expf(dot * SCALE) : 0.f;
                if (val) g_exps[i] = w;
                den += w;
            }
#pragma unroll
            for (int o = 16; o > 0; o >>= 1)
                den += __shfl_xor_sync(0xffffffffu, den, o);
            float invden = 1.f / (den + 1e-8f);
            for (int base = start; base < end; base += 32) {
                int i = base + lane;
                bool val = (i < end);
                float w = val ? g_exps[i] * invden : 0.f;
                int   s = val ? g_perm[i] : g_perm[start];
                int cnt = min(32, end - base);
                int nch = (cnt + 7) >> 3;
                for (int c = 0; c < nch; c++) {
                    int j0 = c * 8;
#pragma unroll
                    for (int jj = 0; jj < 8; jj++) {
                        int j = j0 + jj;
                        float wj = __shfl_sync(0xffffffffu, w, j);
                        int   sj = __shfl_sync(0xffffffffu, s, j);
                        uint2 vp = *(const uint2*)(g_Vb + (size_t)sj * HH + lane * 4);
                        float2 v01 = bf2f2(vp.x), v23 = bf2f2(vp.y);
                        acc.x += wj * v01.x; acc.y += wj * v01.y;
                        acc.z += wj * v23.x; acc.w += wj * v23.y;
                    }
                }
            }
        }
    }
    *(float4*)&g_agg[(size_t)n * HH + lane * 4] = acc;
}

// ---------------- O-GEMM + residual + LayerNorm fused (packed f32x2) ----
__global__ void __launch_bounds__(256) gemm_ln_kernel(
    const float* __restrict__ W, const float* __restrict__ bias,
    const float* __restrict__ emb, const float* __restrict__ gamma,
    const float* __restrict__ beta, float* __restrict__ out)
{
    __shared__ __align__(16) float As[8][64];
    __shared__ __align__(16) float Ws[8][128];

    int tid = threadIdx.x;
    int tx = tid & 31;
    int ty = tid >> 5;
    int blockM = blockIdx.x * 64;

    unsigned long long cp[4][4];
#pragma unroll
    for (int p = 0; p < 4; p++)
#pragma unroll
        for (int j = 0; j < 4; j++) cp[p][j] = 0ull;

    int am = (tid * 2) >> 3;
    int ak = (tid * 2) & 7;
    int gm = blockM + am;
    int wk = tid >> 5;
    int wn = (tid & 31) * 4;

    for (int kk = 0; kk < HH; kk += 8) {
        float a0 = 0.f, a1 = 0.f;
        if (gm < NN) {
            a0 = g_agg[gm * HH + kk + ak];
            a1 = g_agg[gm * HH + kk + ak + 1];
        }
        As[ak][am]     = a0;
        As[ak + 1][am] = a1;
        float4 w = *(const float4*)&W[(kk + wk) * HH + wn];
        *(float4*)&Ws[wk][wn] = w;
        __syncthreads();
#pragma unroll
        for (int k = 0; k < 8; k++) {
            float4 b = *(const float4*)&Ws[k][tx * 4];
            unsigned long long b0 = pack2(b.x, b.x);
            unsigned long long b1 = pack2(b.y, b.y);
            unsigned long long b2 = pack2(b.z, b.z);
            unsigned long long b3 = pack2(b.w, b.w);
            const unsigned long long* ap =
                (const unsigned long long*)&As[k][ty * 8];
#pragma unroll
            for (int p = 0; p < 4; p++) {
                unsigned long long a = ap[p];
                cp[p][0] = fma2(a, b0, cp[p][0]);
                cp[p][1] = fma2(a, b1, cp[p][1]);
                cp[p][2] = fma2(a, b2, cp[p][2]);
                cp[p][3] = fma2(a, b3, cp[p][3]);
            }
        }
        __syncthreads();
    }

    float4 bb  = *(const float4*)&bias[tx * 4];
    float4 gm4 = *(const float4*)&gamma[tx * 4];
    float4 bt4 = *(const float4*)&beta[tx * 4];

    float rows[8][4];
#pragma unroll
    for (int p = 0; p < 4; p++) {
        unpack2(cp[p][0], rows[2*p][0], rows[2*p+1][0]);
        unpack2(cp[p][1], rows[2*p][1], rows[2*p+1][1]);
        unpack2(cp[p][2], rows[2*p][2], rows[2*p+1][2]);
        unpack2(cp[p][3], rows[2*p][3], rows[2*p+1][3]);
    }

#pragma unroll
    for (int i = 0; i < 8; i++) {
        int m = blockM + ty * 8 + i;
        if (m < NN) {
            float4 e = *(const float4*)&emb[m * HH + tx * 4];
            float x0 = rows[i][0] + bb.x + e.x;
            float x1 = rows[i][1] + bb.y + e.y;
            float x2 = rows[i][2] + bb.z + e.z;
            float x3 = rows[i][3] + bb.w + e.w;
            float s = x0 + x1 + x2 + x3;
            float q = x0 * x0 + x1 * x1 + x2 * x2 + x3 * x3;
#pragma unroll
            for (int o = 16; o > 0; o >>= 1) {
                s += __shfl_xor_sync(0xffffffffu, s, o);
                q += __shfl_xor_sync(0xffffffffu, q, o);
            }
            float mean = s * (1.f / 128.f);
            float var  = q * (1.f / 128.f) - mean * mean;
            float r = rsqrtf(var + 1e-5f);
            float4 o4 = make_float4(gm4.x * (x0 - mean) * r + bt4.x,
                                    gm4.y * (x1 - mean) * r + bt4.y,
                                    gm4.z * (x2 - mean) * r + bt4.z,
                                    gm4.w * (x3 - mean) * r + bt4.w);
            *(float4*)&out[m * HH + tx * 4] = o4;
        }
    }
}

// ---------------- launch ----------------
extern "C" void kernel_launch(void* const* d_in, const int* in_sizes, int n_in,
                              void* d_out, int out_size)
{
    const float* phys  = (const float*)d_in[0];
    const float* emb   = (const float*)d_in[1];
    const int*   eidx  = (const int*)  d_in[2];
    const float* Wq    = (const float*)d_in[3];
    const float* bq    = (const float*)d_in[4];
    const float* Wk    = (const float*)d_in[5];
    const float* bk    = (const float*)d_in[6];
    const float* Wv    = (const float*)d_in[7];
    const float* bv    = (const float*)d_in[8];
    const float* Wo    = (const float*)d_in[9];
    const float* bo    = (const float*)d_in[10];
    const float* gamma = (const float*)d_in[11];
    const float* beta  = (const float*)d_in[12];
    float* out = (float*)d_out;

    const int* src = eidx;        // edge_index[0]
    const int* dst = eidx + EE;   // edge_index[1]

    float *Xp, *Qp;
    __nv_bfloat16 *Kbp, *Vbp;
    cudaGetSymbolAddress((void**)&Xp, g_X);
    cudaGetSymbolAddress((void**)&Qp, g_Q);
    cudaGetSymbolAddress((void**)&Kbp, g_Kb);
    cudaGetSymbolAddress((void**)&Vbp, g_Vb);

    const int SMEM_BYTES = SM_FLOATS * 4;   // 26368
    cudaFuncSetAttribute(mma_gemm_kernel,
                         cudaFuncAttributeMaxDynamicSharedMemorySize, SMEM_BYTES);

    zero_cnt_kernel<<<(NN + 255) / 256, 256>>>();
    build_x_kernel<<<(NPAD * KTOT + 255) / 256, 256>>>(phys, emb);

    // Q: fp32 out; K, V: bf16 out (only consumed by edge gathers)
    mma_gemm_kernel<<<NTILES, 256, SMEM_BYTES>>>(Xp, KTOT, NPAD, TT, Wq, bq, Qp, 0);
    mma_gemm_kernel<<<NTILES, 256, SMEM_BYTES>>>(Xp, KTOT, NPAD, TT, Wk, bk, Kbp, 1);
    mma_gemm_kernel<<<NTILES, 256, SMEM_BYTES>>>(emb, HH, NN, HH, Wv, bv, Vbp, 1);

    hist_kernel<<<(EE + 255) / 256, 256>>>(dst);
    scanA_kernel<<<25, 256>>>();
    scanB_kernel<<<1, 32>>>();
    scanC_kernel<<<25, 256>>>();
    scatter_kernel<<<(EE + 255) / 256, 256>>>(src, dst);

    node_attn_kernel<<<(NN + 7) / 8, 256>>>();

    gemm_ln_kernel<<<(NN + 63) / 64, 256>>>(Wo, bo, emb, gamma, beta, out);
}

// round 15
// speedup vs baseline: 2.0186x; 1.4233x over previous
#include <cuda_runtime.h>
#include <cuda_bf16.h>
#include <stdint.h>
#include <math.h>

#define NN 100000
#define NPAD 100096          // 782 tiles of 128
#define NTILES 782
#define EE 1600000
#define HH 128
#define PP 10
#define TT 138               // PP + HH
#define KTOT 144             // K padded (6 chunks of 24)
#define SCALE 0.08838834764831845f   // 1/sqrt(128)

// ---------------- scratch (static __device__, no allocs) ----------------
__device__ float g_X[NPAD * KTOT];  // concat(physics, emb), zero-padded
__device__ float g_Q[NN * HH];
__device__ __nv_bfloat16 g_Kb[NN * HH];   // K in bf16 (gather-only consumer)
__device__ __nv_bfloat16 g_Vb[NN * HH];   // V in bf16 (gather-only consumer)
__device__ float g_exps[EE];        // only used by rare deg>32 path
__device__ float g_agg[NN * HH];
__device__ int   g_cnt[NN];
__device__ int   g_off[NN];
__device__ int   g_perm[EE];        // holds SRC node id, sorted by dst
__device__ int   g_bsum[32];

// ---------------- helpers ----------------
__device__ __forceinline__ uint32_t f2u(float x) { return __float_as_uint(x); }

__device__ __forceinline__ float tf32_round(float x) {
    uint32_t r;
    asm("cvt.rna.tf32.f32 %0, %1;" : "=r"(r) : "f"(x));
    return __uint_as_float(r);
}

// unpack bf16x2 word -> two floats (elem e = low half, elem e+1 = high half)
__device__ __forceinline__ float2 bf2f2(uint32_t p) {
    return make_float2(__uint_as_float(p << 16),
                       __uint_as_float(p & 0xffff0000u));
}

#define MMA_TF32(d, a, b) \
    asm volatile( \
        "mma.sync.aligned.m16n8k8.row.col.f32.tf32.tf32.f32 " \
        "{%0,%1,%2,%3}, {%4,%5,%6,%7}, {%8,%9}, {%0,%1,%2,%3};" \
        : "+f"((d)[0]), "+f"((d)[1]), "+f"((d)[2]), "+f"((d)[3]) \
        : "r"((a)[0]), "r"((a)[1]), "r"((a)[2]), "r"((a)[3]), \
          "r"((b)[0]), "r"((b)[1]))

// ---------------- prep kernels ----------------
__global__ void zero_cnt_kernel() {
    int i = blockIdx.x * blockDim.x + threadIdx.x;
    if (i < NN) g_cnt[i] = 0;
}

// concat(physics, emb) padded to 144 cols, NPAD rows (zeros outside)
__global__ void __launch_bounds__(256) build_x_kernel(
    const float* __restrict__ phys, const float* __restrict__ emb)
{
    int idx = blockIdx.x * blockDim.x + threadIdx.x;
    if (idx >= NPAD * KTOT) return;
    int n = idx / KTOT;
    int c = idx - n * KTOT;
    float v = 0.f;
    if (n < NN) {
        if (c < PP) v = phys[n * PP + c];
        else if (c < TT) v = emb[n * HH + (c - PP)];
    }
    g_X[idx] = v;
}

// ---------------- tf32 mma GEMM: C[128,128] = A @ W + bias -------------
// BM=128, BN=128, BK=24 (6 chunks), 256 threads, 8 warps,
// warp tile 32x64 = 2x8 m16n8k8 tiles; single-pass tf32.
#define SM_AH 0
#define SM_BH 3200
#define SM_BIAS 6464
#define SM_FLOATS 6592

__global__ void __launch_bounds__(256, 2) mma_gemm_kernel(
    const float* __restrict__ A, int ldA, int nrowsA, int kmaxB,
    const float* __restrict__ W, const float* __restrict__ bias,
    void* __restrict__ Cv, int bf16out)
{
    extern __shared__ float sm[];
    float* Ah = sm + SM_AH;
    float* Bh = sm + SM_BH;
    float* bsm = sm + SM_BIAS;

    int tid = threadIdx.x;
    if (tid < 128) bsm[tid] = bias[tid];

    int mbase = blockIdx.x * 128;
    int w = tid >> 5, lane = tid & 31;
    int wm = w & 3, wn = w >> 2;
    int gr = lane >> 2, lc = lane & 3;

    float d[2][8][4];
#pragma unroll
    for (int mt = 0; mt < 2; mt++)
#pragma unroll
        for (int nt = 0; nt < 8; nt++)
#pragma unroll
            for (int j = 0; j < 4; j++) d[mt][nt][j] = 0.f;

    int ar[3], akq[3]; bool arok[3];
    int bk[3], bcq[3];
#pragma unroll
    for (int i = 0; i < 3; i++) {
        int fa = tid + i * 256;
        ar[i] = fa / 6;
        akq[i] = (fa % 6) * 4;
        arok[i] = (mbase + ar[i]) < nrowsA;
        bk[i] = fa >> 5;
        bcq[i] = (fa & 31) << 2;
    }

    for (int ch = 0; ch < 6; ch++) {
        int kk = ch * 24;
        float4 av[3], bv[3];
#pragma unroll
        for (int i = 0; i < 3; i++) {
            bool aok = arok[i] && (kk + akq[i] < ldA);
            av[i] = aok ? *(const float4*)&A[(size_t)(mbase + ar[i]) * ldA + kk + akq[i]]
                        : make_float4(0.f, 0.f, 0.f, 0.f);
            int kg = kk + bk[i];
            bv[i] = (kg < kmaxB) ? *(const float4*)&W[kg * 128 + bcq[i]]
                                 : make_float4(0.f, 0.f, 0.f, 0.f);
        }
        __syncthreads();
#pragma unroll
        for (int i = 0; i < 3; i++) {
            int ab = ar[i] * 25 + akq[i];
            Ah[ab+0] = tf32_round(av[i].x);
            Ah[ab+1] = tf32_round(av[i].y);
            Ah[ab+2] = tf32_round(av[i].z);
            Ah[ab+3] = tf32_round(av[i].w);
            int bb = bk[i] * 136 + bcq[i];
            float4 h4;
            h4.x = tf32_round(bv[i].x);
            h4.y = tf32_round(bv[i].y);
            h4.z = tf32_round(bv[i].z);
            h4.w = tf32_round(bv[i].w);
            *(float4*)&Bh[bb] = h4;
        }
        __syncthreads();

#pragma unroll
        for (int ks = 0; ks < 3; ks++) {
            int kb = ks * 8;
            uint32_t ah[2][4], bh[8][2];
#pragma unroll
            for (int mt = 0; mt < 2; mt++) {
                int base = (wm * 32 + mt * 16 + gr) * 25 + kb + lc;
                ah[mt][0] = f2u(Ah[base]);
                ah[mt][1] = f2u(Ah[base + 8 * 25]);
                ah[mt][2] = f2u(Ah[base + 4]);
                ah[mt][3] = f2u(Ah[base + 8 * 25 + 4]);
            }
#pragma unroll
            for (int nt = 0; nt < 8; nt++) {
                int b0 = (kb + lc) * 136 + wn * 64 + nt * 8 + gr;
                bh[nt][0] = f2u(Bh[b0]);
                bh[nt][1] = f2u(Bh[b0 + 4 * 136]);
            }
#pragma unroll
            for (int mt = 0; mt < 2; mt++)
#pragma unroll
                for (int nt = 0; nt < 8; nt++) MMA_TF32(d[mt][nt], ah[mt], bh[nt]);
        }
    }

    if (!bf16out) {
        float* C = (float*)Cv;
#pragma unroll
        for (int mt = 0; mt < 2; mt++) {
            int r0 = mbase + wm * 32 + mt * 16 + gr;
#pragma unroll
            for (int nt = 0; nt < 8; nt++) {
                int col = wn * 64 + nt * 8 + lc * 2;
                float b0 = bsm[col], b1 = bsm[col + 1];
                if (r0 < NN) {
                    float2 o = make_float2(d[mt][nt][0] + b0, d[mt][nt][1] + b1);
                    *(float2*)&C[(size_t)r0 * HH + col] = o;
                }
                if (r0 + 8 < NN) {
                    float2 o = make_float2(d[mt][nt][2] + b0, d[mt][nt][3] + b1);
                    *(float2*)&C[(size_t)(r0 + 8) * HH + col] = o;
                }
            }
        }
    } else {
        __nv_bfloat16* C = (__nv_bfloat16*)Cv;
#pragma unroll
        for (int mt = 0; mt < 2; mt++) {
            int r0 = mbase + wm * 32 + mt * 16 + gr;
#pragma unroll
            for (int nt = 0; nt < 8; nt++) {
                int col = wn * 64 + nt * 8 + lc * 2;
                float b0 = bsm[col], b1 = bsm[col + 1];
                if (r0 < NN) {
                    __nv_bfloat162 h = __float22bfloat162_rn(
                        make_float2(d[mt][nt][0] + b0, d[mt][nt][1] + b1));
                    *(__nv_bfloat162*)&C[(size_t)r0 * HH + col] = h;
                }
                if (r0 + 8 < NN) {
                    __nv_bfloat162 h = __float22bfloat162_rn(
                        make_float2(d[mt][nt][2] + b0, d[mt][nt][3] + b1));
                    *(__nv_bfloat162*)&C[(size_t)(r0 + 8) * HH + col] = h;
                }
            }
        }
    }
}

// ---------------- tf32 mma GEMM + residual + LayerNorm (out kernel) -----
// A = g_agg [NN,128], W = Wo [128,128]; x = A@W + bo + emb; out = LN(x)
__global__ void __launch_bounds__(256, 2) mma_gemm_ln_kernel(
    const float* __restrict__ W, const float* __restrict__ bias,
    const float* __restrict__ emb, const float* __restrict__ gamma,
    const float* __restrict__ beta, float* __restrict__ out)
{
    extern __shared__ float sm[];
    __shared__ float redS[128][2];
    __shared__ float redQ[128][2];
    float* Ah = sm + SM_AH;
    float* Bh = sm + SM_BH;
    float* bsm = sm + SM_BIAS;

    int tid = threadIdx.x;
    if (tid < 128) bsm[tid] = bias[tid];

    int mbase = blockIdx.x * 128;
    int w = tid >> 5, lane = tid & 31;
    int wm = w & 3, wn = w >> 2;
    int gr = lane >> 2, lc = lane & 3;

    float d[2][8][4];
#pragma unroll
    for (int mt = 0; mt < 2; mt++)
#pragma unroll
        for (int nt = 0; nt < 8; nt++)
#pragma unroll
            for (int j = 0; j < 4; j++) d[mt][nt][j] = 0.f;

    int ar[3], akq[3]; bool arok[3];
    int bk[3], bcq[3];
#pragma unroll
    for (int i = 0; i < 3; i++) {
        int fa = tid + i * 256;
        ar[i] = fa / 6;
        akq[i] = (fa % 6) * 4;
        arok[i] = (mbase + ar[i]) < NN;
        bk[i] = fa >> 5;
        bcq[i] = (fa & 31) << 2;
    }

    for (int ch = 0; ch < 6; ch++) {
        int kk = ch * 24;
        float4 av[3], bv[3];
#pragma unroll
        for (int i = 0; i < 3; i++) {
            bool aok = arok[i] && (kk + akq[i] < HH);
            av[i] = aok ? *(const float4*)&g_agg[(size_t)(mbase + ar[i]) * HH + kk + akq[i]]
                        : make_float4(0.f, 0.f, 0.f, 0.f);
            int kg = kk + bk[i];
            bv[i] = (kg < HH) ? *(const float4*)&W[kg * 128 + bcq[i]]
                              : make_float4(0.f, 0.f, 0.f, 0.f);
        }
        __syncthreads();
#pragma unroll
        for (int i = 0; i < 3; i++) {
            int ab = ar[i] * 25 + akq[i];
            Ah[ab+0] = tf32_round(av[i].x);
            Ah[ab+1] = tf32_round(av[i].y);
            Ah[ab+2] = tf32_round(av[i].z);
            Ah[ab+3] = tf32_round(av[i].w);
            int bb = bk[i] * 136 + bcq[i];
            float4 h4;
            h4.x = tf32_round(bv[i].x);
            h4.y = tf32_round(bv[i].y);
            h4.z = tf32_round(bv[i].z);
            h4.w = tf32_round(bv[i].w);
            *(float4*)&Bh[bb] = h4;
        }
        __syncthreads();

#pragma unroll
        for (int ks = 0; ks < 3; ks++) {
            int kb = ks * 8;
            uint32_t ah[2][4], bh[8][2];
#pragma unroll
            for (int mt = 0; mt < 2; mt++) {
                int base = (wm * 32 + mt * 16 + gr) * 25 + kb + lc;
                ah[mt][0] = f2u(Ah[base]);
                ah[mt][1] = f2u(Ah[base + 8 * 25]);
                ah[mt][2] = f2u(Ah[base + 4]);
                ah[mt][3] = f2u(Ah[base + 8 * 25 + 4]);
            }
#pragma unroll
            for (int nt = 0; nt < 8; nt++) {
                int b0 = (kb + lc) * 136 + wn * 64 + nt * 8 + gr;
                bh[nt][0] = f2u(Bh[b0]);
                bh[nt][1] = f2u(Bh[b0 + 4 * 136]);
            }
#pragma unroll
            for (int mt = 0; mt < 2; mt++)
#pragma unroll
                for (int nt = 0; nt < 8; nt++) MMA_TF32(d[mt][nt], ah[mt], bh[nt]);
        }
    }

    // ---- LN epilogue ----
    // pass 1: x = d + bias + residual (overwrite d), partial row sums
#pragma unroll
    for (int mt = 0; mt < 2; mt++) {
#pragma unroll
        for (int half = 0; half < 2; half++) {
            int rl = wm * 32 + mt * 16 + gr + half * 8;
            int row = mbase + rl;
            float s = 0.f, q = 0.f;
#pragma unroll
            for (int nt = 0; nt < 8; nt++) {
                int col = wn * 64 + nt * 8 + lc * 2;
                float2 e = (row < NN) ? *(const float2*)&emb[(size_t)row * HH + col]
                                      : make_float2(0.f, 0.f);
                float x0 = d[mt][nt][half * 2 + 0] + bsm[col] + e.x;
                float x1 = d[mt][nt][half * 2 + 1] + bsm[col + 1] + e.y;
                d[mt][nt][half * 2 + 0] = x0;
                d[mt][nt][half * 2 + 1] = x1;
                s += x0 + x1;
                q += x0 * x0 + x1 * x1;
            }
            // reduce over lc (4 consecutive lanes)
            s += __shfl_xor_sync(0xffffffffu, s, 1);
            s += __shfl_xor_sync(0xffffffffu, s, 2);
            q += __shfl_xor_sync(0xffffffffu, q, 1);
            q += __shfl_xor_sync(0xffffffffu, q, 2);
            if (lc == 0) { redS[rl][wn] = s; redQ[rl][wn] = q; }
        }
    }
    __syncthreads();

    // pass 2: normalize + write
#pragma unroll
    for (int mt = 0; mt < 2; mt++) {
#pragma unroll
        for (int half = 0; half < 2; half++) {
            int rl = wm * 32 + mt * 16 + gr + half * 8;
            int row = mbase + rl;
            if (row < NN) {
                float s = redS[rl][0] + redS[rl][1];
                float q = redQ[rl][0] + redQ[rl][1];
                float mean = s * (1.f / 128.f);
                float var  = q * (1.f / 128.f) - mean * mean;
                float r = rsqrtf(var + 1e-5f);
#pragma unroll
                for (int nt = 0; nt < 8; nt++) {
                    int col = wn * 64 + nt * 8 + lc * 2;
                    float2 g = *(const float2*)&gamma[col];
                    float2 b = *(const float2*)&beta[col];
                    float2 o;
                    o.x = g.x * (d[mt][nt][half * 2 + 0] - mean) * r + b.x;
                    o.y = g.y * (d[mt][nt][half * 2 + 1] - mean) * r + b.y;
                    *(float2*)&out[(size_t)row * HH + col] = o;
                }
            }
        }
    }
}

// ---------------- histogram of dst ----------------
__global__ void __launch_bounds__(256) hist_kernel(const int* __restrict__ dst) {
    int e = blockIdx.x * blockDim.x + threadIdx.x;
    if (e < EE) atomicAdd(&g_cnt[dst[e]], 1);
}

// ---------------- exclusive scan of g_cnt -> g_off (3 kernels) ----------
__global__ void __launch_bounds__(256) scanA_kernel() {
    __shared__ int wsumI[8];
    int base = blockIdx.x * 4096;
    int t = threadIdx.x;
    int idx0 = base + t * 16;
    int vals[16];
    int s = 0;
#pragma unroll
    for (int j = 0; j < 16; j++) {
        int idx = idx0 + j;
        int v = (idx < NN) ? g_cnt[idx] : 0;
        vals[j] = s;
        s += v;
    }
    int lane = t & 31, wid = t >> 5;
    int incl = s;
#pragma unroll
    for (int o = 1; o < 32; o <<= 1) {
        int v = __shfl_up_sync(0xffffffffu, incl, o);
        if (lane >= o) incl += v;
    }
    if (lane == 31) wsumI[wid] = incl;
    __syncthreads();
    if (wid == 0) {
        int w = (lane < 8) ? wsumI[lane] : 0;
#pragma unroll
        for (int o = 1; o < 8; o <<= 1) {
            int v = __shfl_up_sync(0xffffffffu, w, o);
            if (lane >= o) w += v;
        }
        if (lane < 8) wsumI[lane] = w;
    }
    __syncthreads();
    int texcl = (incl - s) + (wid > 0 ? wsumI[wid - 1] : 0);
#pragma unroll
    for (int j = 0; j < 16; j++) {
        int idx = idx0 + j;
        if (idx < NN) g_off[idx] = texcl + vals[j];
    }
    if (t == 0) g_bsum[blockIdx.x] = wsumI[7];
}

__global__ void scanB_kernel() {
    if (threadIdx.x == 0) {
        int s = 0;
#pragma unroll
        for (int i = 0; i < 25; i++) { int v = g_bsum[i]; g_bsum[i] = s; s += v; }
    }
}

__global__ void __launch_bounds__(256) scanC_kernel() {
    int add = g_bsum[blockIdx.x];
    int idx0 = blockIdx.x * 4096 + threadIdx.x * 16;
#pragma unroll
    for (int j = 0; j < 16; j++) {
        int idx = idx0 + j;
        if (idx < NN) g_off[idx] += add;
    }
}

// ---------------- scatter SRC ids into CSR slots (mutates g_off) --------
__global__ void __launch_bounds__(256) scatter_kernel(const int* __restrict__ src,
                                                      const int* __restrict__ dst) {
    int e = blockIdx.x * blockDim.x + threadIdx.x;
    if (e >= EE) return;
    int d = dst[e];
    int p = atomicAdd(&g_off[d], 1);
    g_perm[p] = src[e];
}

// ---------------- fused per-node: scores + softmax + aggregation --------
// one warp per node. BOTH K and V phases are warp-cooperative per edge:
// all 32 lanes load their 8B column slice of the edge's K/V row (one
// coalesced 256B access per edge), so L1 wavefronts/edge = 8, not 32x32.
// The reduced dot is uniform across lanes -> den accumulates uniformly.
__global__ void __launch_bounds__(256) node_attn_kernel() {
    int n = blockIdx.x * 8 + (threadIdx.x >> 5);
    if (n >= NN) return;
    int lane = threadIdx.x & 31;
    int end = g_off[n];
    int start = (n == 0) ? 0 : g_off[n - 1];
    int deg = end - start;

    float4 acc = make_float4(0.f, 0.f, 0.f, 0.f);

    if (deg > 0) {
        float4 q = *(const float4*)&g_Q[(size_t)n * HH + lane * 4];

        if (deg <= 32) {
            int s = (lane < deg) ? g_perm[start + lane] : g_perm[start];
            float w = 0.f, den = 0.f;
            int nch = (deg + 7) >> 3;
            for (int c = 0; c < nch; c++) {
                int j0 = c * 8;
                uint2 kp[8];
#pragma unroll
                for (int jj = 0; jj < 8; jj++) {
                    int sj = __shfl_sync(0xffffffffu, s, j0 + jj);
                    kp[jj] = *(const uint2*)(g_Kb + (size_t)sj * HH + lane * 4);
                }
#pragma unroll
                for (int jj = 0; jj < 8; jj++) {
                    int j = j0 + jj;
                    float2 k01 = bf2f2(kp[jj].x), k23 = bf2f2(kp[jj].y);
                    float p = q.x * k01.x + q.y * k01.y + q.z * k23.x + q.w * k23.y;
#pragma unroll
                    for (int o = 16; o > 0; o >>= 1)
                        p += __shfl_xor_sync(0xffffffffu, p, o);
                    float e = (j < deg) ? expf(p * SCALE) : 0.f;
                    den += e;                    // uniform across lanes
                    if (lane == j) w = e;
                }
            }
            w *= 1.f / (den + 1e-8f);
            for (int c = 0; c < nch; c++) {
                int j0 = c * 8;
#pragma unroll
                for (int jj = 0; jj < 8; jj++) {
                    int j = j0 + jj;
                    float wj = __shfl_sync(0xffffffffu, w, j);
                    int   sj = __shfl_sync(0xffffffffu, s, j);
                    uint2 vp = *(const uint2*)(g_Vb + (size_t)sj * HH + lane * 4);
                    float2 v01 = bf2f2(vp.x), v23 = bf2f2(vp.y);
                    acc.x += wj * v01.x; acc.y += wj * v01.y;
                    acc.z += wj * v23.x; acc.w += wj * v23.y;
                }
            }
        } else {
            // rare path (deg>32): cooperative per edge, stage exps in gmem
            float den = 0.f;
            for (int i = start; i < end; i++) {
                int sj = g_perm[i];   // uniform broadcast load
                uint2 kp = *(const uint2*)(g_Kb + (size_t)sj * HH + lane * 4);
                float2 k01 = bf2f2(kp.x), k23 = bf2f2(kp.y);
                float p = q.x * k01.x + q.y * k01.y + q.z * k23.x + q.w * k23.y;
#pragma unroll
                for (int o = 16; o > 0; o >>= 1)
                    p += __shfl_xor_sync(0xffffffffu, p, o);
                float e = expf(p * SCALE);
                den += e;
                if (lane == 0) g_exps[i] = e;
            }
            float invden = 1.f / (den + 1e-8f);
            for (int i = start; i < end; i++) {
                float wj = g_exps[i] * invden;   // uniform
                int   sj = g_perm[i];
                uint2 vp = *(const uint2*)(g_Vb + (size_t)sj * HH + lane * 4);
                float2 v01 = bf2f2(vp.x), v23 = bf2f2(vp.y);
                acc.x += wj * v01.x; acc.y += wj * v01.y;
                acc.z += wj * v23.x; acc.w += wj * v23.y;
            }
        }
    }
    *(float4*)&g_agg[(size_t)n * HH + lane * 4] = acc;
}

// ---------------- launch ----------------
extern "C" void kernel_launch(void* const* d_in, const int* in_sizes, int n_in,
                              void* d_out, int out_size)
{
    const float* phys  = (const float*)d_in[0];
    const float* emb   = (const float*)d_in[1];
    const int*   eidx  = (const int*)  d_in[2];
    const float* Wq    = (const float*)d_in[3];
    const float* bq    = (const float*)d_in[4];
    const float* Wk    = (const float*)d_in[5];
    const float* bk    = (const float*)d_in[6];
    const float* Wv    = (const float*)d_in[7];
    const float* bv    = (const float*)d_in[8];
    const float* Wo    = (const float*)d_in[9];
    const float* bo    = (const float*)d_in[10];
    const float* gamma = (const float*)d_in[11];
    const float* beta  = (const float*)d_in[12];
    float* out = (float*)d_out;

    const int* src = eidx;        // edge_index[0]
    const int* dst = eidx + EE;   // edge_index[1]

    float *Xp, *Qp;
    __nv_bfloat16 *Kbp, *Vbp;
    cudaGetSymbolAddress((void**)&Xp, g_X);
    cudaGetSymbolAddress((void**)&Qp, g_Q);
    cudaGetSymbolAddress((void**)&Kbp, g_Kb);
    cudaGetSymbolAddress((void**)&Vbp, g_Vb);

    const int SMEM_BYTES = SM_FLOATS * 4;   // 26368
    cudaFuncSetAttribute(mma_gemm_kernel,
                         cudaFuncAttributeMaxDynamicSharedMemorySize, SMEM_BYTES);
    cudaFuncSetAttribute(mma_gemm_ln_kernel,
                         cudaFuncAttributeMaxDynamicSharedMemorySize, SMEM_BYTES);

    zero_cnt_kernel<<<(NN + 255) / 256, 256>>>();
    build_x_kernel<<<(NPAD * KTOT + 255) / 256, 256>>>(phys, emb);

    // Q: fp32 out; K, V: bf16 out (only consumed by edge gathers)
    mma_gemm_kernel<<<NTILES, 256, SMEM_BYTES>>>(Xp, KTOT, NPAD, TT, Wq, bq, Qp, 0);
    mma_gemm_kernel<<<NTILES, 256, SMEM_BYTES>>>(Xp, KTOT, NPAD, TT, Wk, bk, Kbp, 1);
    mma_gemm_kernel<<<NTILES, 256, SMEM_BYTES>>>(emb, HH, NN, HH, Wv, bv, Vbp, 1);

    hist_kernel<<<(EE + 255) / 256, 256>>>(dst);
    scanA_kernel<<<25, 256>>>();
    scanB_kernel<<<1, 32>>>();
    scanC_kernel<<<25, 256>>>();
    scatter_kernel<<<(EE + 255) / 256, 256>>>(src, dst);

    node_attn_kernel<<<(NN + 7) / 8, 256>>>();

    mma_gemm_ln_kernel<<<NTILES, 256, SMEM_BYTES>>>(Wo, bo, emb, gamma, beta, out);
}